// round 13
// baseline (speedup 1.0000x reference)
#include <cuda_runtime.h>

#define KK 30
#define NNODE 16384
#define NEDGE (NNODE * KK)   // 491520
#define CH 148
#define NT 8
#define AS 120               // packed activation stride: 100 s + 16 vn + 4 zero

// ---------------- device scratch (no allocation) ----------------
__device__ float g_dh[(size_t)NNODE * CH];
__device__ float g_sVs[(size_t)NNODE * 100];
__device__ float g_vn1[(size_t)NEDGE * 32];
__device__ float g_s1[(size_t)NEDGE * AS];
__device__ float g_s2[(size_t)NEDGE * AS];
// B planes (tf32 hi/lo), pair-interleaved: [(k*4+t)][n][2] = rows (8k+t, 8k+t+4)
__device__ float g_B1hi[17 * 4 * 104 * 2], g_B1lo[17 * 4 * 104 * 2];
__device__ float g_B2hi[15 * 4 * 104 * 2], g_B2lo[15 * 4 * 104 * 2];
__device__ float g_B3hi[15 * 4 * 104 * 2], g_B3lo[15 * 4 * 104 * 2];

__device__ __forceinline__ float sigmoidf_(float x) { return 1.0f / (1.0f + expf(-x)); }

__device__ __forceinline__ unsigned tf32_rna(float f) {
    unsigned u; asm("cvt.rna.tf32.f32 %0, %1;" : "=r"(u) : "f"(f)); return u;
}

__device__ __forceinline__ void mma_tf32(float& c0, float& c1, float& c2, float& c3,
                                         unsigned a0, unsigned a1, unsigned a2, unsigned a3,
                                         unsigned b0, unsigned b1) {
    asm volatile("mma.sync.aligned.m16n8k8.row.col.f32.tf32.tf32.f32 "
                 "{%0,%1,%2,%3},{%4,%5,%6,%7},{%8,%9},{%0,%1,%2,%3};"
                 : "+f"(c0), "+f"(c1), "+f"(c2), "+f"(c3)
                 : "r"(a0), "r"(a1), "r"(a2), "r"(a3), "r"(b0), "r"(b1));
}

// ---------------- prep: tf32 hi/lo planes, pair-interleaved ----------------
// out idx = ((k*4+t)*104 + n)*2 + half ; source row = 8k + t + 4*half
__global__ void prep_kernel(const float* __restrict__ Ws1,
                            const float* __restrict__ Ws2,
                            const float* __restrict__ Ws3) {
    int tid = blockIdx.x * blockDim.x + threadIdx.x;
    int stride = gridDim.x * blockDim.x;
    for (int idx = tid; idx < 17 * 4 * 104 * 2; idx += stride) {
        int kq = idx / 208, rem = idx - kq * 208;
        int n = rem >> 1, half = rem & 1;
        int row = (kq >> 2) * 8 + (kq & 3) + half * 4;
        float v = (row < 132 && n < 100) ? Ws1[(size_t)(100 + row) * 100 + n] : 0.f;
        unsigned hi = tf32_rna(v);
        g_B1hi[idx] = __uint_as_float(hi);
        g_B1lo[idx] = __uint_as_float(tf32_rna(v - __uint_as_float(hi)));
    }
    for (int idx = tid; idx < 15 * 4 * 104 * 2; idx += stride) {
        int kq = idx / 208, rem = idx - kq * 208;
        int n = rem >> 1, half = rem & 1;
        int row = (kq >> 2) * 8 + (kq & 3) + half * 4;
        float v2 = (row < 116 && n < 100) ? Ws2[(size_t)row * 100 + n] : 0.f;
        unsigned hi2 = tf32_rna(v2);
        g_B2hi[idx] = __uint_as_float(hi2);
        g_B2lo[idx] = __uint_as_float(tf32_rna(v2 - __uint_as_float(hi2)));
        float v3 = (row < 116 && n < 100) ? Ws3[(size_t)row * 100 + n] : 0.f;
        unsigned hi3 = tf32_rna(v3);
        g_B3hi[idx] = __uint_as_float(hi3);
        g_B3lo[idx] = __uint_as_float(tf32_rna(v3 - __uint_as_float(hi3)));
    }
}

// ---------------- vector-track kernel (per node) ----------------
template <int NI, int NH>
__device__ __forceinline__ void vh_stage(
    const float* __restrict__ vin, int vinstride,
    const float* __restrict__ Wh, const float* __restrict__ init,
    float* __restrict__ vh, int vhstride,
    float* __restrict__ vn_g, int vnstride, int tid)
{
    for (int idx = tid; idx < KK * NH; idx += 128) {
        int e = idx / NH;
        int h = idx - e * NH;
        float a0 = 0.f, a1 = 0.f, a2 = 0.f;
        if (init) { a0 = init[h * 3 + 0]; a1 = init[h * 3 + 1]; a2 = init[h * 3 + 2]; }
        const float* vp = vin + e * vinstride;
#pragma unroll
        for (int i = 0; i < NI; i++) {
            float w = Wh[i * NH + h];
            a0 = fmaf(vp[3 * i + 0], w, a0);
            a1 = fmaf(vp[3 * i + 1], w, a1);
            a2 = fmaf(vp[3 * i + 2], w, a2);
        }
        float* vo = vh + e * vhstride + h * 3;
        vo[0] = a0; vo[1] = a1; vo[2] = a2;
        vn_g[(size_t)e * vnstride + h] = sqrtf(fmaf(a0, a0, fmaf(a1, a1, a2 * a2)) + 1e-8f);
    }
}

template <int NH, bool GATE>
__device__ __forceinline__ void vout_stage(
    const float* __restrict__ vh, int vhstride,
    const float* __restrict__ Wv, float* __restrict__ vout, int tid)
{
    for (int idx = tid; idx < KK * 16; idx += 128) {
        int e = idx >> 4;
        int o = idx & 15;
        float a0 = 0.f, a1 = 0.f, a2 = 0.f;
        const float* vp = vh + e * vhstride;
#pragma unroll
        for (int h = 0; h < NH; h++) {
            float w = Wv[h * 16 + o];
            a0 = fmaf(vp[3 * h + 0], w, a0);
            a1 = fmaf(vp[3 * h + 1], w, a1);
            a2 = fmaf(vp[3 * h + 2], w, a2);
        }
        if (GATE) {
            float n = sqrtf(fmaf(a0, a0, fmaf(a1, a1, a2 * a2)) + 1e-8f);
            float g = sigmoidf_(n);
            a0 *= g; a1 *= g; a2 *= g;
        }
        float* vo = vout + e * 48 + o * 3;
        vo[0] = a0; vo[1] = a1; vo[2] = a2;
    }
}

// smem offsets (floats)
#define VA_VM   0
#define VA_VH   1440
#define VA_V    4320
#define VA_HV   5760
#define VA_VVH  5912
#define VA_MASK 6008
#define VA_WH1  6040
#define VA_WV1  7064
#define VA_WH2  7576
#define VA_WV2  7832
#define VA_WH3  8088
#define VA_WV3  8344
#define VA_TOT  8600

__global__ void __launch_bounds__(128, 5) vec_kernel(
    const float* __restrict__ hV, const float* __restrict__ hM,
    const int* __restrict__ maskA,
    const float* __restrict__ Wh1, const float* __restrict__ Wv1,
    const float* __restrict__ Ws1, const float* __restrict__ bs1,
    const float* __restrict__ Wh2, const float* __restrict__ Wv2,
    const float* __restrict__ Wh3, const float* __restrict__ Wv3,
    float* __restrict__ s1p, float* __restrict__ s2p)
{
    extern __shared__ float sm[];
    float* vM_s  = sm + VA_VM;
    float* vh_s  = sm + VA_VH;
    float* v_s   = sm + VA_V;
    float* hV_s  = sm + VA_HV;
    float* vVh_s = sm + VA_VVH;
    float* mask_s= sm + VA_MASK;
    float* Wh1_s = sm + VA_WH1;
    float* Wv1_s = sm + VA_WV1;
    float* Wh2_s = sm + VA_WH2;
    float* Wv2_s = sm + VA_WV2;
    float* Wh3_s = sm + VA_WH3;
    float* Wv3_s = sm + VA_WV3;

    const int tid = threadIdx.x;
    const int node = blockIdx.x;
    const float* hMb = hM + (size_t)node * KK * CH;

    for (int idx = tid; idx < KK * 12; idx += 128) {
        int e = idx / 12, q = idx - e * 12;
        *(float4*)&vM_s[e * 48 + q * 4] = *(const float4*)(hMb + (size_t)e * CH + q * 4);
    }
    for (int i = tid; i < CH; i += 128) hV_s[i] = hV[(size_t)node * CH + i];
    if (tid < KK) mask_s[tid] = (float)maskA[(size_t)node * KK + tid];
    // zero the pad columns (116..119) of both packed activation buffers
    for (int idx = tid; idx < KK * 4; idx += 128) {
        int e = idx >> 2, q = idx & 3;
        s1p[((size_t)node * KK + e) * AS + 116 + q] = 0.f;
        s2p[((size_t)node * KK + e) * AS + 116 + q] = 0.f;
    }
    for (int i = tid; i < 1024; i += 128) Wh1_s[i] = Wh1[i];
    for (int i = tid; i < 512; i += 128) Wv1_s[i] = Wv1[i];
    for (int i = tid; i < 256; i += 128) {
        Wh2_s[i] = Wh2[i]; Wv2_s[i] = Wv2[i];
        Wh3_s[i] = Wh3[i]; Wv3_s[i] = Wv3[i];
    }
    __syncthreads();

    if (tid < 96) {
        int h = tid / 3, c = tid - h * 3;
        float a = 0.f;
#pragma unroll
        for (int i = 0; i < 16; i++) a = fmaf(hV_s[3 * i + c], Wh1_s[i * 32 + h], a);
        vVh_s[h * 3 + c] = a;
    }
    if (tid < 100) {
        float a = bs1[tid];
#pragma unroll 4
        for (int p = 0; p < 100; p++) a = fmaf(hV_s[48 + p], Ws1[(size_t)p * 100 + tid], a);
        g_sVs[(size_t)node * 100 + tid] = a;
    }
    __syncthreads();

    vh_stage<16, 32>(vM_s, 48, Wh1_s + 16 * 32, vVh_s, vh_s, 96,
                     g_vn1 + (size_t)node * KK * 32, 32, tid);
    __syncthreads();
    vout_stage<32, true>(vh_s, 96, Wv1_s, v_s, tid);
    __syncthreads();
    vh_stage<16, 16>(v_s, 48, Wh2_s, nullptr, vh_s, 48,
                     s1p + (size_t)node * KK * AS + 100, AS, tid);
    __syncthreads();
    vout_stage<16, true>(vh_s, 48, Wv2_s, v_s, tid);
    __syncthreads();
    vh_stage<16, 16>(v_s, 48, Wh3_s, nullptr, vh_s, 48,
                     s2p + (size_t)node * KK * AS + 100, AS, tid);
    __syncthreads();
    vout_stage<16, false>(vh_s, 48, Wv3_s, v_s, tid);
    __syncthreads();

    if (tid < 48) {
        float a = 0.f;
#pragma unroll
        for (int e = 0; e < KK; e++) a = fmaf(mask_s[e], v_s[e * 48 + tid], a);
        g_dh[(size_t)node * CH + tid] = a * (1.0f / 30.0f);
    }
}

// ---------------- tf32 3x GEMM over all edges ----------------
template <int W2, bool PACKED>
__device__ __forceinline__ float loadA(const float* __restrict__ srcS, int strideS, int offS,
                                       const float* __restrict__ srcV, int r, int c)
{
    if (PACKED) return srcS[(size_t)r * AS + c];
    if (c < 100) return srcS[(size_t)r * strideS + offS + c];
    if (c < 100 + W2) return srcV[(size_t)r * W2 + (c - 100)];
    return 0.f;
}

template <int KSTEPS, int W2, bool RELU, bool INIT_SVS, bool PACKED, int NJ>
__device__ __forceinline__ void gemm_core(
    const float* __restrict__ srcS, int strideS, int offS,
    const float* __restrict__ srcV,
    const float* Bhi, const float* Blo,
    const float* __restrict__ initv,
    float* __restrict__ outp,
    int m0, int j0, int gid, int tig)
{
    float acc[2][NJ][4] = {};
    float fcur[2][4];
#pragma unroll
    for (int t = 0; t < 2; t++) {
        int r0 = m0 + t * 16 + gid, r1 = r0 + 8;
        fcur[t][0] = loadA<W2, PACKED>(srcS, strideS, offS, srcV, r0, tig);
        fcur[t][1] = loadA<W2, PACKED>(srcS, strideS, offS, srcV, r1, tig);
        fcur[t][2] = loadA<W2, PACKED>(srcS, strideS, offS, srcV, r0, tig + 4);
        fcur[t][3] = loadA<W2, PACKED>(srcS, strideS, offS, srcV, r1, tig + 4);
    }
#pragma unroll 1
    for (int k = 0; k < KSTEPS; k++) {
        unsigned ahi[2][4], alo[2][4];
#pragma unroll
        for (int t = 0; t < 2; t++)
#pragma unroll
            for (int q = 0; q < 4; q++) {
                ahi[t][q] = tf32_rna(fcur[t][q]);
                alo[t][q] = tf32_rna(fcur[t][q] - __uint_as_float(ahi[t][q]));
            }
        if (k + 1 < KSTEPS) {
#pragma unroll
            for (int t = 0; t < 2; t++) {
                int r0 = m0 + t * 16 + gid, r1 = r0 + 8;
                int cA = (k + 1) * 8 + tig, cB = cA + 4;
                fcur[t][0] = loadA<W2, PACKED>(srcS, strideS, offS, srcV, r0, cA);
                fcur[t][1] = loadA<W2, PACKED>(srcS, strideS, offS, srcV, r1, cA);
                fcur[t][2] = loadA<W2, PACKED>(srcS, strideS, offS, srcV, r0, cB);
                fcur[t][3] = loadA<W2, PACKED>(srcS, strideS, offS, srcV, r1, cB);
            }
        }
        const float2* Bh2 = (const float2*)Bhi;
        const float2* Bl2 = (const float2*)Blo;
        int bbase = (k * 4 + tig) * 104;
#pragma unroll
        for (int jj = 0; jj < NJ; jj++) {
            int n0 = (j0 + jj) * 8 + gid;
            float2 bh = Bh2[bbase + n0];
            float2 bl = Bl2[bbase + n0];
            unsigned bh0 = __float_as_uint(bh.x), bh1 = __float_as_uint(bh.y);
            unsigned bl0 = __float_as_uint(bl.x), bl1 = __float_as_uint(bl.y);
#pragma unroll
            for (int t = 0; t < 2; t++) {
                mma_tf32(acc[t][jj][0], acc[t][jj][1], acc[t][jj][2], acc[t][jj][3],
                         ahi[t][0], ahi[t][1], ahi[t][2], ahi[t][3], bh0, bh1);
                mma_tf32(acc[t][jj][0], acc[t][jj][1], acc[t][jj][2], acc[t][jj][3],
                         ahi[t][0], ahi[t][1], ahi[t][2], ahi[t][3], bl0, bl1);
                mma_tf32(acc[t][jj][0], acc[t][jj][1], acc[t][jj][2], acc[t][jj][3],
                         alo[t][0], alo[t][1], alo[t][2], alo[t][3], bh0, bh1);
            }
        }
    }
    // epilogue: write cols 0..99 at stride AS
#pragma unroll
    for (int t = 0; t < 2; t++) {
        int r0 = m0 + t * 16 + gid, r1 = r0 + 8;
#pragma unroll
        for (int jj = 0; jj < NJ; jj++) {
            int c0 = (j0 + jj) * 8 + tig * 2;
            if (c0 < 100) {
                float i00, i01, i10, i11;
                if (INIT_SVS) {
                    const float* p0 = initv + (size_t)(r0 / 30) * 100;
                    const float* p1 = initv + (size_t)(r1 / 30) * 100;
                    i00 = p0[c0]; i01 = p0[c0 + 1];
                    i10 = p1[c0]; i11 = p1[c0 + 1];
                } else {
                    i00 = initv[c0]; i01 = initv[c0 + 1];
                    i10 = i00; i11 = i01;
                }
                float v00 = acc[t][jj][0] + i00;
                float v01 = acc[t][jj][1] + i01;
                float v10 = acc[t][jj][2] + i10;
                float v11 = acc[t][jj][3] + i11;
                if (RELU) {
                    v00 = fmaxf(v00, 0.f); v01 = fmaxf(v01, 0.f);
                    v10 = fmaxf(v10, 0.f); v11 = fmaxf(v11, 0.f);
                }
                *(float2*)&outp[(size_t)r0 * AS + c0] = make_float2(v00, v01);
                *(float2*)&outp[(size_t)r1 * AS + c0] = make_float2(v10, v11);
            }
        }
    }
}

template <int KSTEPS, int W2, bool RELU, bool INIT_SVS, bool PACKED>
__global__ void __launch_bounds__(512, 1) gemm_kernel(
    const float* __restrict__ srcS, int strideS, int offS,
    const float* __restrict__ srcV,
    const float* __restrict__ Bhi_g, const float* __restrict__ Blo_g,
    const float* __restrict__ initv,
    float* __restrict__ outp)
{
    extern __shared__ float smemB[];
    float* Bhi = smemB;
    float* Blo = smemB + KSTEPS * 8 * 104;
    const int tid = threadIdx.x;
    const int nB = KSTEPS * 8 * 104;
    for (int i = tid * 4; i < nB; i += 512 * 4) {
        *(float4*)&Bhi[i] = *(const float4*)&Bhi_g[i];
        *(float4*)&Blo[i] = *(const float4*)&Blo_g[i];
    }
    __syncthreads();

    const int warp = tid >> 5, lane = tid & 31;
    const int gid = lane >> 2, tig = lane & 3;
    const int mw = warp & 7, ng = warp >> 3;
    const int m0 = blockIdx.x * 256 + mw * 32;

    if (ng == 0)
        gemm_core<KSTEPS, W2, RELU, INIT_SVS, PACKED, 7>(srcS, strideS, offS, srcV,
                                                         Bhi, Blo, initv, outp, m0, 0, gid, tig);
    else
        gemm_core<KSTEPS, W2, RELU, INIT_SVS, PACKED, 6>(srcS, strideS, offS, srcV,
                                                         Bhi, Blo, initv, outp, m0, 7, gid, tig);
}

// ---------------- masked mean of s3 -> g_dh scalar part ----------------
__global__ void __launch_bounds__(128) reduce_kernel(const int* __restrict__ maskA,
                                                     const float* __restrict__ s3)
{
    int node = blockIdx.x;
    int j = threadIdx.x;
    if (j < 100) {
        const float* base = s3 + (size_t)node * KK * AS + j;
        const int* mb = maskA + (size_t)node * KK;
        float a = 0.f;
#pragma unroll
        for (int e = 0; e < KK; e++) a = fmaf((float)mb[e], base[(size_t)e * AS], a);
        g_dh[(size_t)node * CH + 48 + j] = a * (1.0f / 30.0f);
    }
}

// ---------------- node kernel (unchanged) ----------------
__global__ void __launch_bounds__(128, 4) node_kernel(
    const float* __restrict__ hV, const int* __restrict__ maskV,
    const float* __restrict__ Wh4, const float* __restrict__ Wv4,
    const float* __restrict__ Ws4, const float* __restrict__ bs4,
    const float* __restrict__ Wh5, const float* __restrict__ Wv5,
    const float* __restrict__ Ws5, const float* __restrict__ bs5,
    const float* __restrict__ ln0g, const float* __restrict__ ln0b,
    const float* __restrict__ ln1g, const float* __restrict__ ln1b,
    float* __restrict__ out)
{
    __shared__ __align__(16) float hbuf[NT][CH];
    __shared__ __align__(16) float vh[NT][96];
    __shared__ __align__(16) float vn[NT][32];
    __shared__ __align__(16) float s4[NT][400];
    __shared__ __align__(16) float v4[NT][96];
    __shared__ __align__(16) float s5[NT][100];
    __shared__ __align__(16) float v5[NT][48];
    __shared__ float Wh4s[512], Wv4s[1024], Wh5s[1024], Wv5s[512];

    const int tid = threadIdx.x;
    const int nb = blockIdx.x * NT;

    for (int i = tid; i < 512; i += 128) { Wh4s[i] = Wh4[i]; Wv5s[i] = Wv5[i]; }
    for (int i = tid; i < 1024; i += 128) { Wv4s[i] = Wv4[i]; Wh5s[i] = Wh5[i]; }
    for (int idx = tid; idx < NT * CH; idx += 128) {
        int n = idx / CH, c = idx - n * CH;
        hbuf[n][c] = hV[(size_t)(nb + n) * CH + c] + g_dh[(size_t)(nb + n) * CH + c];
    }
    __syncthreads();

    {
        int n = tid >> 4, l = tid & 15;
        float* xb = hbuf[n];
        float x0 = xb[3 * l], x1 = xb[3 * l + 1], x2 = xb[3 * l + 2];
        float vv = fmaf(x0, x0, fmaf(x1, x1, x2 * x2));
#pragma unroll
        for (int o = 8; o > 0; o >>= 1) vv += __shfl_xor_sync(0xffffffffu, vv, o, 16);
        float rden = rsqrtf(vv * (1.0f / 16.0f) + 1e-8f);
        float sum = 0.f, sum2 = 0.f;
        for (int p = l; p < 100; p += 16) { float v = xb[48 + p]; sum += v; sum2 = fmaf(v, v, sum2); }
#pragma unroll
        for (int o = 8; o > 0; o >>= 1) {
            sum  += __shfl_xor_sync(0xffffffffu, sum, o, 16);
            sum2 += __shfl_xor_sync(0xffffffffu, sum2, o, 16);
        }
        float mu = sum * 0.01f;
        float var = sum2 * 0.01f - mu * mu;
        float rstd = rsqrtf(var + 1e-5f);
        xb[3 * l] = x0 * rden; xb[3 * l + 1] = x1 * rden; xb[3 * l + 2] = x2 * rden;
        for (int p = l; p < 100; p += 16)
            xb[48 + p] = fmaf((xb[48 + p] - mu) * rstd, ln0g[p], ln0b[p]);
    }
    __syncthreads();

    for (int idx = tid; idx < NT * 32; idx += 128) {
        int n = idx >> 5, h = idx & 31;
        float a0 = 0.f, a1 = 0.f, a2 = 0.f;
        const float* vp = hbuf[n];
#pragma unroll
        for (int i = 0; i < 16; i++) {
            float w = Wh4s[i * 32 + h];
            a0 = fmaf(vp[3 * i], w, a0); a1 = fmaf(vp[3 * i + 1], w, a1); a2 = fmaf(vp[3 * i + 2], w, a2);
        }
        vh[n][h * 3] = a0; vh[n][h * 3 + 1] = a1; vh[n][h * 3 + 2] = a2;
        vn[n][h] = sqrtf(fmaf(a0, a0, fmaf(a1, a1, a2 * a2)) + 1e-8f);
    }
    __syncthreads();

    for (int r = 0; r < 4; r++) {
        int j = r * 128 + tid;
        if (j < 400) {
            float acc[NT];
            float b = bs4[j];
#pragma unroll
            for (int n = 0; n < NT; n++) acc[n] = b;
#pragma unroll 2
            for (int p = 0; p < 100; p += 4) {
                float w0 = Ws4[(p + 0) * 400 + j], w1 = Ws4[(p + 1) * 400 + j];
                float w2 = Ws4[(p + 2) * 400 + j], w3 = Ws4[(p + 3) * 400 + j];
#pragma unroll
                for (int n = 0; n < NT; n++) {
                    float4 sv = *(const float4*)&hbuf[n][48 + p];
                    acc[n] = fmaf(sv.x, w0, fmaf(sv.y, w1, fmaf(sv.z, w2, fmaf(sv.w, w3, acc[n]))));
                }
            }
#pragma unroll 2
            for (int p = 0; p < 32; p += 4) {
                float w0 = Ws4[(100 + p) * 400 + j], w1 = Ws4[(101 + p) * 400 + j];
                float w2 = Ws4[(102 + p) * 400 + j], w3 = Ws4[(103 + p) * 400 + j];
#pragma unroll
                for (int n = 0; n < NT; n++) {
                    float4 sv = *(const float4*)&vn[n][p];
                    acc[n] = fmaf(sv.x, w0, fmaf(sv.y, w1, fmaf(sv.z, w2, fmaf(sv.w, w3, acc[n]))));
                }
            }
#pragma unroll
            for (int n = 0; n < NT; n++) s4[n][j] = fmaxf(acc[n], 0.0f);
        }
    }
    __syncthreads();

    for (int idx = tid; idx < NT * 32; idx += 128) {
        int n = idx >> 5, o = idx & 31;
        float a0 = 0.f, a1 = 0.f, a2 = 0.f;
#pragma unroll
        for (int h = 0; h < 32; h++) {
            float w = Wv4s[h * 32 + o];
            a0 = fmaf(vh[n][3 * h], w, a0); a1 = fmaf(vh[n][3 * h + 1], w, a1); a2 = fmaf(vh[n][3 * h + 2], w, a2);
        }
        float nn = sqrtf(fmaf(a0, a0, fmaf(a1, a1, a2 * a2)) + 1e-8f);
        float g = sigmoidf_(nn);
        v4[n][o * 3] = a0 * g; v4[n][o * 3 + 1] = a1 * g; v4[n][o * 3 + 2] = a2 * g;
    }
    __syncthreads();

    for (int idx = tid; idx < NT * 32; idx += 128) {
        int n = idx >> 5, h = idx & 31;
        float a0 = 0.f, a1 = 0.f, a2 = 0.f;
#pragma unroll
        for (int i = 0; i < 32; i++) {
            float w = Wh5s[i * 32 + h];
            a0 = fmaf(v4[n][3 * i], w, a0); a1 = fmaf(v4[n][3 * i + 1], w, a1); a2 = fmaf(v4[n][3 * i + 2], w, a2);
        }
        vh[n][h * 3] = a0; vh[n][h * 3 + 1] = a1; vh[n][h * 3 + 2] = a2;
        vn[n][h] = sqrtf(fmaf(a0, a0, fmaf(a1, a1, a2 * a2)) + 1e-8f);
    }
    __syncthreads();

    if (tid < 100) {
        int j = tid;
        float acc[NT];
        float b = bs5[j];
#pragma unroll
        for (int n = 0; n < NT; n++) acc[n] = b;
#pragma unroll 2
        for (int p = 0; p < 400; p += 4) {
            float w0 = Ws5[(p + 0) * 100 + j], w1 = Ws5[(p + 1) * 100 + j];
            float w2 = Ws5[(p + 2) * 100 + j], w3 = Ws5[(p + 3) * 100 + j];
#pragma unroll
            for (int n = 0; n < NT; n++) {
                float4 sv = *(const float4*)&s4[n][p];
                acc[n] = fmaf(sv.x, w0, fmaf(sv.y, w1, fmaf(sv.z, w2, fmaf(sv.w, w3, acc[n]))));
            }
        }
#pragma unroll 2
        for (int p = 0; p < 32; p += 4) {
            float w0 = Ws5[(400 + p) * 100 + j], w1 = Ws5[(401 + p) * 100 + j];
            float w2 = Ws5[(402 + p) * 100 + j], w3 = Ws5[(403 + p) * 100 + j];
#pragma unroll
            for (int n = 0; n < NT; n++) {
                float4 sv = *(const float4*)&vn[n][p];
                acc[n] = fmaf(sv.x, w0, fmaf(sv.y, w1, fmaf(sv.z, w2, fmaf(sv.w, w3, acc[n]))));
            }
        }
#pragma unroll
        for (int n = 0; n < NT; n++) s5[n][j] = acc[n];
    }
    __syncthreads();

    {
        int n = tid >> 4, o = tid & 15;
        float a0 = 0.f, a1 = 0.f, a2 = 0.f;
#pragma unroll
        for (int h = 0; h < 32; h++) {
            float w = Wv5s[h * 16 + o];
            a0 = fmaf(vh[n][3 * h], w, a0); a1 = fmaf(vh[n][3 * h + 1], w, a1); a2 = fmaf(vh[n][3 * h + 2], w, a2);
        }
        v5[n][o * 3] = a0; v5[n][o * 3 + 1] = a1; v5[n][o * 3 + 2] = a2;
    }
    __syncthreads();

    {
        int n = tid >> 4, l = tid & 15;
        float* xb = hbuf[n];
        float x0 = xb[3 * l] + v5[n][3 * l];
        float x1 = xb[3 * l + 1] + v5[n][3 * l + 1];
        float x2 = xb[3 * l + 2] + v5[n][3 * l + 2];
        float vv = fmaf(x0, x0, fmaf(x1, x1, x2 * x2));
#pragma unroll
        for (int o = 8; o > 0; o >>= 1) vv += __shfl_xor_sync(0xffffffffu, vv, o, 16);
        float rden = rsqrtf(vv * (1.0f / 16.0f) + 1e-8f);
        float sum = 0.f, sum2 = 0.f;
        float svv[7];
        int cnt = 0;
        for (int p = l; p < 100; p += 16) {
            float v = xb[48 + p] + s5[n][p];
            svv[cnt++] = v;
            sum += v; sum2 = fmaf(v, v, sum2);
        }
#pragma unroll
        for (int o = 8; o > 0; o >>= 1) {
            sum  += __shfl_xor_sync(0xffffffffu, sum, o, 16);
            sum2 += __shfl_xor_sync(0xffffffffu, sum2, o, 16);
        }
        float mu = sum * 0.01f;
        float var = sum2 * 0.01f - mu * mu;
        float rstd = rsqrtf(var + 1e-5f);
        float mk = (float)maskV[nb + n];
        float* op = out + (size_t)(nb + n) * CH;
        op[3 * l]     = mk * x0 * rden;
        op[3 * l + 1] = mk * x1 * rden;
        op[3 * l + 2] = mk * x2 * rden;
        cnt = 0;
        for (int p = l; p < 100; p += 16)
            op[48 + p] = mk * fmaf((svv[cnt++] - mu) * rstd, ln1g[p], ln1b[p]);
    }
}

// no-op pads: shift the ncu sample (in-call position 3) onto vec_kernel
__global__ void pad_kernel() {}

extern "C" void kernel_launch(void* const* d_in, const int* in_sizes, int n_in,
                              void* d_out, int out_size) {
    const float* hV    = (const float*)d_in[0];
    const float* hM    = (const float*)d_in[1];
    const int*   maskV = (const int*)d_in[2];
    const int*   maskA = (const int*)d_in[3];
    const float* Wh1 = (const float*)d_in[4];
    const float* Wv1 = (const float*)d_in[5];
    const float* Ws1 = (const float*)d_in[6];
    const float* bs1 = (const float*)d_in[7];
    const float* Wh2 = (const float*)d_in[8];
    const float* Wv2 = (const float*)d_in[9];
    const float* Ws2 = (const float*)d_in[10];
    const float* bs2 = (const float*)d_in[11];
    const float* Wh3 = (const float*)d_in[12];
    const float* Wv3 = (const float*)d_in[13];
    const float* Ws3 = (const float*)d_in[14];
    const float* bs3 = (const float*)d_in[15];
    const float* Wh4 = (const float*)d_in[16];
    const float* Wv4 = (const float*)d_in[17];
    const float* Ws4 = (const float*)d_in[18];
    const float* bs4 = (const float*)d_in[19];
    const float* Wh5 = (const float*)d_in[20];
    const float* Wv5 = (const float*)d_in[21];
    const float* Ws5 = (const float*)d_in[22];
    const float* bs5 = (const float*)d_in[23];
    const float* ln0g = (const float*)d_in[24];
    const float* ln0b = (const float*)d_in[25];
    const float* ln1g = (const float*)d_in[26];
    const float* ln1b = (const float*)d_in[27];
    float* out = (float*)d_out;

    float* s1p; cudaGetSymbolAddress((void**)&s1p, g_s1);
    float* s2p; cudaGetSymbolAddress((void**)&s2p, g_s2);
    float* vn1p; cudaGetSymbolAddress((void**)&vn1p, g_vn1);
    float* sVsp; cudaGetSymbolAddress((void**)&sVsp, g_sVs);
    float* b1h; cudaGetSymbolAddress((void**)&b1h, g_B1hi);
    float* b1l; cudaGetSymbolAddress((void**)&b1l, g_B1lo);
    float* b2h; cudaGetSymbolAddress((void**)&b2h, g_B2hi);
    float* b2l; cudaGetSymbolAddress((void**)&b2l, g_B2lo);
    float* b3h; cudaGetSymbolAddress((void**)&b3h, g_B3hi);
    float* b3l; cudaGetSymbolAddress((void**)&b3l, g_B3lo);

    const int smemA = VA_TOT * 4;
    const int smemG1 = 2 * 17 * 8 * 104 * 4;
    const int smemG23 = 2 * 15 * 8 * 104 * 4;
    cudaFuncSetAttribute(vec_kernel, cudaFuncAttributeMaxDynamicSharedMemorySize, smemA);
    cudaFuncSetAttribute(gemm_kernel<17, 32, true, true, false>,
                         cudaFuncAttributeMaxDynamicSharedMemorySize, smemG1);
    cudaFuncSetAttribute(gemm_kernel<15, 16, true, false, true>,
                         cudaFuncAttributeMaxDynamicSharedMemorySize, smemG23);
    cudaFuncSetAttribute(gemm_kernel<15, 16, false, false, true>,
                         cudaFuncAttributeMaxDynamicSharedMemorySize, smemG23);

    pad_kernel<<<1, 32>>>();
    pad_kernel<<<1, 32>>>();
    prep_kernel<<<52, 256>>>(Ws1, Ws2, Ws3);
    vec_kernel<<<NNODE, 128, smemA>>>(hV, hM, maskA, Wh1, Wv1, Ws1, bs1,
                                      Wh2, Wv2, Wh3, Wv3, s1p, s2p);
    gemm_kernel<17, 32, true, true, false><<<NEDGE / 256, 512, smemG1>>>(
        hM, CH, 48, vn1p, b1h, b1l, sVsp, s1p);
    gemm_kernel<15, 16, true, false, true><<<NEDGE / 256, 512, smemG23>>>(
        s1p, 0, 0, nullptr, b2h, b2l, bs2, s2p);
    gemm_kernel<15, 16, false, false, true><<<NEDGE / 256, 512, smemG23>>>(
        s2p, 0, 0, nullptr, b3h, b3l, bs3, s1p);
    reduce_kernel<<<NNODE, 128>>>(maskA, s1p);
    node_kernel<<<NNODE / NT, 128>>>(
        hV, maskV, Wh4, Wv4, Ws4, bs4, Wh5, Wv5, Ws5, bs5,
        ln0g, ln0b, ln1g, ln1b, out);
}

// round 15
// speedup vs baseline: 1.4077x; 1.4077x over previous
#include <cuda_runtime.h>

#define KK 30
#define NNODE 16384
#define NEDGE (NNODE * KK)   // 491520
#define CH 148
#define NT 8

// ---------------- device scratch (no allocation) ----------------
__device__ float g_dh[(size_t)NNODE * CH];
__device__ float g_sVs[(size_t)NNODE * 100];
__device__ float g_vn1[(size_t)NEDGE * 32];
__device__ float g_vn2[(size_t)NEDGE * 16];
__device__ float g_vn3[(size_t)NEDGE * 16];
__device__ float g_s1[(size_t)NEDGE * 100];
__device__ float g_s2[(size_t)NEDGE * 100];
// B planes (tf32 hi/lo), padded [K_pad][104]
__device__ float g_B1hi[17 * 8 * 104], g_B1lo[17 * 8 * 104];
__device__ float g_B2hi[15 * 8 * 104], g_B2lo[15 * 8 * 104];
__device__ float g_B3hi[15 * 8 * 104], g_B3lo[15 * 8 * 104];

__device__ __forceinline__ float sigmoidf_(float x) { return 1.0f / (1.0f + expf(-x)); }

__device__ __forceinline__ unsigned tf32_rna(float f) {
    unsigned u; asm("cvt.rna.tf32.f32 %0, %1;" : "=r"(u) : "f"(f)); return u;
}

__device__ __forceinline__ void mma_tf32(float& c0, float& c1, float& c2, float& c3,
                                         unsigned a0, unsigned a1, unsigned a2, unsigned a3,
                                         unsigned b0, unsigned b1) {
    asm volatile("mma.sync.aligned.m16n8k8.row.col.f32.tf32.tf32.f32 "
                 "{%0,%1,%2,%3},{%4,%5,%6,%7},{%8,%9},{%0,%1,%2,%3};"
                 : "+f"(c0), "+f"(c1), "+f"(c2), "+f"(c3)
                 : "r"(a0), "r"(a1), "r"(a2), "r"(a3), "r"(b0), "r"(b1));
}

// ---------------- prep: tf32 hi/lo planes of the scalar weights ----------------
__global__ void prep_kernel(const float* __restrict__ Ws1,
                            const float* __restrict__ Ws2,
                            const float* __restrict__ Ws3) {
    int tid = blockIdx.x * blockDim.x + threadIdx.x;
    int stride = gridDim.x * blockDim.x;
    for (int idx = tid; idx < 17 * 8 * 104; idx += stride) {
        int k = idx / 104, n = idx - k * 104;
        float v = (k < 132 && n < 100) ? Ws1[(size_t)(100 + k) * 100 + n] : 0.f;
        unsigned hi = tf32_rna(v);
        g_B1hi[idx] = __uint_as_float(hi);
        g_B1lo[idx] = __uint_as_float(tf32_rna(v - __uint_as_float(hi)));
    }
    for (int idx = tid; idx < 15 * 8 * 104; idx += stride) {
        int k = idx / 104, n = idx - k * 104;
        float v2 = (k < 116 && n < 100) ? Ws2[(size_t)k * 100 + n] : 0.f;
        unsigned hi2 = tf32_rna(v2);
        g_B2hi[idx] = __uint_as_float(hi2);
        g_B2lo[idx] = __uint_as_float(tf32_rna(v2 - __uint_as_float(hi2)));
        float v3 = (k < 116 && n < 100) ? Ws3[(size_t)k * 100 + n] : 0.f;
        unsigned hi3 = tf32_rna(v3);
        g_B3hi[idx] = __uint_as_float(hi3);
        g_B3lo[idx] = __uint_as_float(tf32_rna(v3 - __uint_as_float(hi3)));
    }
}

// ---------------- vector-track kernel (per node) ----------------
// vp reads float4-ized: 12 LDS.128 replace 48 scalar LDS per item.
template <int NI, int NH>
__device__ __forceinline__ void vh_stage(
    const float* __restrict__ vin, int vinstride,
    const float* __restrict__ Wh, const float* __restrict__ init,
    float* __restrict__ vh, int vhstride,
    float* __restrict__ vn_g, int tid)
{
    for (int idx = tid; idx < KK * NH; idx += 128) {
        int e = idx / NH;
        int h = idx - e * NH;
        float a0 = 0.f, a1 = 0.f, a2 = 0.f;
        if (init) { a0 = init[h * 3 + 0]; a1 = init[h * 3 + 1]; a2 = init[h * 3 + 2]; }
        const float4* vp4 = (const float4*)(vin + e * vinstride);
#pragma unroll
        for (int q = 0; q < NI / 4; q++) {
            float4 A = vp4[3 * q + 0];
            float4 B = vp4[3 * q + 1];
            float4 C = vp4[3 * q + 2];
            float w0 = Wh[(4 * q + 0) * NH + h];
            float w1 = Wh[(4 * q + 1) * NH + h];
            float w2 = Wh[(4 * q + 2) * NH + h];
            float w3 = Wh[(4 * q + 3) * NH + h];
            a0 = fmaf(A.x, w0, a0); a1 = fmaf(A.y, w0, a1); a2 = fmaf(A.z, w0, a2);
            a0 = fmaf(A.w, w1, a0); a1 = fmaf(B.x, w1, a1); a2 = fmaf(B.y, w1, a2);
            a0 = fmaf(B.z, w2, a0); a1 = fmaf(B.w, w2, a1); a2 = fmaf(C.x, w2, a2);
            a0 = fmaf(C.y, w3, a0); a1 = fmaf(C.z, w3, a1); a2 = fmaf(C.w, w3, a2);
        }
        float* vo = vh + e * vhstride + h * 3;
        vo[0] = a0; vo[1] = a1; vo[2] = a2;
        vn_g[(size_t)e * NH + h] = sqrtf(fmaf(a0, a0, fmaf(a1, a1, a2 * a2)) + 1e-8f);
    }
}

template <int NH, bool GATE>
__device__ __forceinline__ void vout_stage(
    const float* __restrict__ vh, int vhstride,
    const float* __restrict__ Wv, float* __restrict__ vout, int tid)
{
    for (int idx = tid; idx < KK * 16; idx += 128) {
        int e = idx >> 4;
        int o = idx & 15;
        float a0 = 0.f, a1 = 0.f, a2 = 0.f;
        const float4* vp4 = (const float4*)(vh + e * vhstride);
#pragma unroll
        for (int q = 0; q < NH / 4; q++) {
            float4 A = vp4[3 * q + 0];
            float4 B = vp4[3 * q + 1];
            float4 C = vp4[3 * q + 2];
            float w0 = Wv[(4 * q + 0) * 16 + o];
            float w1 = Wv[(4 * q + 1) * 16 + o];
            float w2 = Wv[(4 * q + 2) * 16 + o];
            float w3 = Wv[(4 * q + 3) * 16 + o];
            a0 = fmaf(A.x, w0, a0); a1 = fmaf(A.y, w0, a1); a2 = fmaf(A.z, w0, a2);
            a0 = fmaf(A.w, w1, a0); a1 = fmaf(B.x, w1, a1); a2 = fmaf(B.y, w1, a2);
            a0 = fmaf(B.z, w2, a0); a1 = fmaf(B.w, w2, a1); a2 = fmaf(C.x, w2, a2);
            a0 = fmaf(C.y, w3, a0); a1 = fmaf(C.z, w3, a1); a2 = fmaf(C.w, w3, a2);
        }
        if (GATE) {
            float n = sqrtf(fmaf(a0, a0, fmaf(a1, a1, a2 * a2)) + 1e-8f);
            float g = sigmoidf_(n);
            a0 *= g; a1 *= g; a2 *= g;
        }
        float* vo = vout + e * 48 + o * 3;
        vo[0] = a0; vo[1] = a1; vo[2] = a2;
    }
}

// smem offsets (floats) -- all float4-aligned
#define VA_VM   0
#define VA_VH   1440
#define VA_V    4320
#define VA_HV   5760
#define VA_VVH  5912
#define VA_MASK 6008
#define VA_WH1  6040
#define VA_WV1  7064
#define VA_WH2  7576
#define VA_WV2  7832
#define VA_WH3  8088
#define VA_WV3  8344
#define VA_TOT  8600

__global__ void __launch_bounds__(128, 5) vec_kernel(
    const float* __restrict__ hV, const float* __restrict__ hM,
    const int* __restrict__ maskA,
    const float* __restrict__ Wh1, const float* __restrict__ Wv1,
    const float* __restrict__ Ws1, const float* __restrict__ bs1,
    const float* __restrict__ Wh2, const float* __restrict__ Wv2,
    const float* __restrict__ Wh3, const float* __restrict__ Wv3)
{
    extern __shared__ float sm[];
    float* vM_s  = sm + VA_VM;
    float* vh_s  = sm + VA_VH;
    float* v_s   = sm + VA_V;
    float* hV_s  = sm + VA_HV;
    float* vVh_s = sm + VA_VVH;
    float* mask_s= sm + VA_MASK;
    float* Wh1_s = sm + VA_WH1;
    float* Wv1_s = sm + VA_WV1;
    float* Wh2_s = sm + VA_WH2;
    float* Wv2_s = sm + VA_WV2;
    float* Wh3_s = sm + VA_WH3;
    float* Wv3_s = sm + VA_WV3;

    const int tid = threadIdx.x;
    const int node = blockIdx.x;
    const float* hMb = hM + (size_t)node * KK * CH;

    for (int idx = tid; idx < KK * 12; idx += 128) {
        int e = idx / 12, q = idx - e * 12;
        *(float4*)&vM_s[e * 48 + q * 4] = *(const float4*)(hMb + (size_t)e * CH + q * 4);
    }
    for (int i = tid; i < CH; i += 128) hV_s[i] = hV[(size_t)node * CH + i];
    if (tid < KK) mask_s[tid] = (float)maskA[(size_t)node * KK + tid];
    for (int i = tid; i < 1024; i += 128) Wh1_s[i] = Wh1[i];
    for (int i = tid; i < 512; i += 128) Wv1_s[i] = Wv1[i];
    for (int i = tid; i < 256; i += 128) {
        Wh2_s[i] = Wh2[i]; Wv2_s[i] = Wv2[i];
        Wh3_s[i] = Wh3[i]; Wv3_s[i] = Wv3[i];
    }
    __syncthreads();

    if (tid < 96) {
        int h = tid / 3, c = tid - h * 3;
        float a = 0.f;
#pragma unroll
        for (int i = 0; i < 16; i++) a = fmaf(hV_s[3 * i + c], Wh1_s[i * 32 + h], a);
        vVh_s[h * 3 + c] = a;
    }
    if (tid < 100) {
        float a = bs1[tid];
#pragma unroll 4
        for (int p = 0; p < 100; p++) a = fmaf(hV_s[48 + p], Ws1[(size_t)p * 100 + tid], a);
        g_sVs[(size_t)node * 100 + tid] = a;
    }
    __syncthreads();

    vh_stage<16, 32>(vM_s, 48, Wh1_s + 16 * 32, vVh_s, vh_s, 96,
                     g_vn1 + (size_t)node * KK * 32, tid);
    __syncthreads();
    vout_stage<32, true>(vh_s, 96, Wv1_s, v_s, tid);
    __syncthreads();
    vh_stage<16, 16>(v_s, 48, Wh2_s, nullptr, vh_s, 48,
                     g_vn2 + (size_t)node * KK * 16, tid);
    __syncthreads();
    vout_stage<16, true>(vh_s, 48, Wv2_s, v_s, tid);
    __syncthreads();
    vh_stage<16, 16>(v_s, 48, Wh3_s, nullptr, vh_s, 48,
                     g_vn3 + (size_t)node * KK * 16, tid);
    __syncthreads();
    vout_stage<16, false>(vh_s, 48, Wv3_s, v_s, tid);
    __syncthreads();

    if (tid < 48) {
        float a = 0.f;
#pragma unroll
        for (int e = 0; e < KK; e++) a = fmaf(mask_s[e], v_s[e * 48 + tid], a);
        g_dh[(size_t)node * CH + tid] = a * (1.0f / 30.0f);
    }
}

// ---------------- tf32 3x GEMM over all edges (round-9 form) ----------------
#define LOADA(r, c) \
    ((c) < 100 ? srcS[(size_t)(r) * strideS + offS + (c)] \
               : ((c) < 100 + W2 ? srcV[(size_t)(r) * W2 + ((c) - 100)] : 0.f))

template <int KSTEPS, int W2, bool RELU, bool INIT_SVS, int NJ>
__device__ __forceinline__ void gemm_core(
    const float* __restrict__ srcS, int strideS, int offS,
    const float* __restrict__ srcV,
    const float* Bhi, const float* Blo,
    const float* __restrict__ initv,
    float* __restrict__ outp,
    int m0, int j0, int gid, int tig)
{
    float acc[2][NJ][4] = {};
    float fcur[2][4];
#pragma unroll
    for (int t = 0; t < 2; t++) {
        int r0 = m0 + t * 16 + gid, r1 = r0 + 8;
        int cA = tig, cB = tig + 4;
        fcur[t][0] = LOADA(r0, cA);
        fcur[t][1] = LOADA(r1, cA);
        fcur[t][2] = LOADA(r0, cB);
        fcur[t][3] = LOADA(r1, cB);
    }
#pragma unroll 1
    for (int k = 0; k < KSTEPS; k++) {
        unsigned ahi[2][4], alo[2][4];
#pragma unroll
        for (int t = 0; t < 2; t++)
#pragma unroll
            for (int q = 0; q < 4; q++) {
                ahi[t][q] = tf32_rna(fcur[t][q]);
                alo[t][q] = tf32_rna(fcur[t][q] - __uint_as_float(ahi[t][q]));
            }
        if (k + 1 < KSTEPS) {
#pragma unroll
            for (int t = 0; t < 2; t++) {
                int r0 = m0 + t * 16 + gid, r1 = r0 + 8;
                int cA = (k + 1) * 8 + tig, cB = cA + 4;
                fcur[t][0] = LOADA(r0, cA);
                fcur[t][1] = LOADA(r1, cA);
                fcur[t][2] = LOADA(r0, cB);
                fcur[t][3] = LOADA(r1, cB);
            }
        }
#pragma unroll
        for (int jj = 0; jj < NJ; jj++) {
            int n0 = (j0 + jj) * 8 + gid;
            unsigned bh0 = __float_as_uint(Bhi[(k * 8 + tig) * 104 + n0]);
            unsigned bh1 = __float_as_uint(Bhi[(k * 8 + tig + 4) * 104 + n0]);
            unsigned bl0 = __float_as_uint(Blo[(k * 8 + tig) * 104 + n0]);
            unsigned bl1 = __float_as_uint(Blo[(k * 8 + tig + 4) * 104 + n0]);
#pragma unroll
            for (int t = 0; t < 2; t++) {
                mma_tf32(acc[t][jj][0], acc[t][jj][1], acc[t][jj][2], acc[t][jj][3],
                         ahi[t][0], ahi[t][1], ahi[t][2], ahi[t][3], bh0, bh1);
                mma_tf32(acc[t][jj][0], acc[t][jj][1], acc[t][jj][2], acc[t][jj][3],
                         ahi[t][0], ahi[t][1], ahi[t][2], ahi[t][3], bl0, bl1);
                mma_tf32(acc[t][jj][0], acc[t][jj][1], acc[t][jj][2], acc[t][jj][3],
                         alo[t][0], alo[t][1], alo[t][2], alo[t][3], bh0, bh1);
            }
        }
    }
#pragma unroll
    for (int t = 0; t < 2; t++) {
        int r0 = m0 + t * 16 + gid, r1 = r0 + 8;
#pragma unroll
        for (int jj = 0; jj < NJ; jj++) {
            int c0 = (j0 + jj) * 8 + tig * 2;
            if (c0 < 100) {
                float i00, i01, i10, i11;
                if (INIT_SVS) {
                    const float* p0 = initv + (size_t)(r0 / 30) * 100;
                    const float* p1 = initv + (size_t)(r1 / 30) * 100;
                    i00 = p0[c0]; i01 = p0[c0 + 1];
                    i10 = p1[c0]; i11 = p1[c0 + 1];
                } else {
                    i00 = initv[c0]; i01 = initv[c0 + 1];
                    i10 = i00; i11 = i01;
                }
                float v00 = acc[t][jj][0] + i00;
                float v01 = acc[t][jj][1] + i01;
                float v10 = acc[t][jj][2] + i10;
                float v11 = acc[t][jj][3] + i11;
                if (RELU) {
                    v00 = fmaxf(v00, 0.f); v01 = fmaxf(v01, 0.f);
                    v10 = fmaxf(v10, 0.f); v11 = fmaxf(v11, 0.f);
                }
                *(float2*)&outp[(size_t)r0 * 100 + c0] = make_float2(v00, v01);
                *(float2*)&outp[(size_t)r1 * 100 + c0] = make_float2(v10, v11);
            }
        }
    }
}

template <int KSTEPS, int W2, bool RELU, bool INIT_SVS>
__global__ void __launch_bounds__(512, 1) gemm_kernel(
    const float* __restrict__ srcS, int strideS, int offS,
    const float* __restrict__ srcV,
    const float* __restrict__ Bhi_g, const float* __restrict__ Blo_g,
    const float* __restrict__ initv,
    float* __restrict__ outp)
{
    extern __shared__ float smemB[];
    float* Bhi = smemB;
    float* Blo = smemB + KSTEPS * 8 * 104;
    const int tid = threadIdx.x;
    const int nB = KSTEPS * 8 * 104;
    for (int i = tid * 4; i < nB; i += 512 * 4) {
        *(float4*)&Bhi[i] = *(const float4*)&Bhi_g[i];
        *(float4*)&Blo[i] = *(const float4*)&Blo_g[i];
    }
    __syncthreads();

    const int warp = tid >> 5, lane = tid & 31;
    const int gid = lane >> 2, tig = lane & 3;
    const int mw = warp & 7, ng = warp >> 3;
    const int m0 = blockIdx.x * 256 + mw * 32;

    if (ng == 0)
        gemm_core<KSTEPS, W2, RELU, INIT_SVS, 7>(srcS, strideS, offS, srcV,
                                                 Bhi, Blo, initv, outp, m0, 0, gid, tig);
    else
        gemm_core<KSTEPS, W2, RELU, INIT_SVS, 6>(srcS, strideS, offS, srcV,
                                                 Bhi, Blo, initv, outp, m0, 7, gid, tig);
}

// ---------------- masked mean of s3 -> g_dh scalar part ----------------
__global__ void __launch_bounds__(128) reduce_kernel(const int* __restrict__ maskA,
                                                     const float* __restrict__ s3)
{
    int node = blockIdx.x;
    int j = threadIdx.x;
    if (j < 100) {
        const float* base = s3 + (size_t)node * KK * 100 + j;
        const int* mb = maskA + (size_t)node * KK;
        float a = 0.f;
#pragma unroll
        for (int e = 0; e < KK; e++) a = fmaf((float)mb[e], base[(size_t)e * 100], a);
        g_dh[(size_t)node * CH + 48 + j] = a * (1.0f / 30.0f);
    }
}

// ---------------- node kernel (unchanged) ----------------
__global__ void __launch_bounds__(128, 4) node_kernel(
    const float* __restrict__ hV, const int* __restrict__ maskV,
    const float* __restrict__ Wh4, const float* __restrict__ Wv4,
    const float* __restrict__ Ws4, const float* __restrict__ bs4,
    const float* __restrict__ Wh5, const float* __restrict__ Wv5,
    const float* __restrict__ Ws5, const float* __restrict__ bs5,
    const float* __restrict__ ln0g, const float* __restrict__ ln0b,
    const float* __restrict__ ln1g, const float* __restrict__ ln1b,
    float* __restrict__ out)
{
    __shared__ __align__(16) float hbuf[NT][CH];
    __shared__ __align__(16) float vh[NT][96];
    __shared__ __align__(16) float vn[NT][32];
    __shared__ __align__(16) float s4[NT][400];
    __shared__ __align__(16) float v4[NT][96];
    __shared__ __align__(16) float s5[NT][100];
    __shared__ __align__(16) float v5[NT][48];
    __shared__ float Wh4s[512], Wv4s[1024], Wh5s[1024], Wv5s[512];

    const int tid = threadIdx.x;
    const int nb = blockIdx.x * NT;

    for (int i = tid; i < 512; i += 128) { Wh4s[i] = Wh4[i]; Wv5s[i] = Wv5[i]; }
    for (int i = tid; i < 1024; i += 128) { Wv4s[i] = Wv4[i]; Wh5s[i] = Wh5[i]; }
    for (int idx = tid; idx < NT * CH; idx += 128) {
        int n = idx / CH, c = idx - n * CH;
        hbuf[n][c] = hV[(size_t)(nb + n) * CH + c] + g_dh[(size_t)(nb + n) * CH + c];
    }
    __syncthreads();

    {
        int n = tid >> 4, l = tid & 15;
        float* xb = hbuf[n];
        float x0 = xb[3 * l], x1 = xb[3 * l + 1], x2 = xb[3 * l + 2];
        float vv = fmaf(x0, x0, fmaf(x1, x1, x2 * x2));
#pragma unroll
        for (int o = 8; o > 0; o >>= 1) vv += __shfl_xor_sync(0xffffffffu, vv, o, 16);
        float rden = rsqrtf(vv * (1.0f / 16.0f) + 1e-8f);
        float sum = 0.f, sum2 = 0.f;
        for (int p = l; p < 100; p += 16) { float v = xb[48 + p]; sum += v; sum2 = fmaf(v, v, sum2); }
#pragma unroll
        for (int o = 8; o > 0; o >>= 1) {
            sum  += __shfl_xor_sync(0xffffffffu, sum, o, 16);
            sum2 += __shfl_xor_sync(0xffffffffu, sum2, o, 16);
        }
        float mu = sum * 0.01f;
        float var = sum2 * 0.01f - mu * mu;
        float rstd = rsqrtf(var + 1e-5f);
        xb[3 * l] = x0 * rden; xb[3 * l + 1] = x1 * rden; xb[3 * l + 2] = x2 * rden;
        for (int p = l; p < 100; p += 16)
            xb[48 + p] = fmaf((xb[48 + p] - mu) * rstd, ln0g[p], ln0b[p]);
    }
    __syncthreads();

    for (int idx = tid; idx < NT * 32; idx += 128) {
        int n = idx >> 5, h = idx & 31;
        float a0 = 0.f, a1 = 0.f, a2 = 0.f;
        const float* vp = hbuf[n];
#pragma unroll
        for (int i = 0; i < 16; i++) {
            float w = Wh4s[i * 32 + h];
            a0 = fmaf(vp[3 * i], w, a0); a1 = fmaf(vp[3 * i + 1], w, a1); a2 = fmaf(vp[3 * i + 2], w, a2);
        }
        vh[n][h * 3] = a0; vh[n][h * 3 + 1] = a1; vh[n][h * 3 + 2] = a2;
        vn[n][h] = sqrtf(fmaf(a0, a0, fmaf(a1, a1, a2 * a2)) + 1e-8f);
    }
    __syncthreads();

    for (int r = 0; r < 4; r++) {
        int j = r * 128 + tid;
        if (j < 400) {
            float acc[NT];
            float b = bs4[j];
#pragma unroll
            for (int n = 0; n < NT; n++) acc[n] = b;
#pragma unroll 2
            for (int p = 0; p < 100; p += 4) {
                float w0 = Ws4[(p + 0) * 400 + j], w1 = Ws4[(p + 1) * 400 + j];
                float w2 = Ws4[(p + 2) * 400 + j], w3 = Ws4[(p + 3) * 400 + j];
#pragma unroll
                for (int n = 0; n < NT; n++) {
                    float4 sv = *(const float4*)&hbuf[n][48 + p];
                    acc[n] = fmaf(sv.x, w0, fmaf(sv.y, w1, fmaf(sv.z, w2, fmaf(sv.w, w3, acc[n]))));
                }
            }
#pragma unroll 2
            for (int p = 0; p < 32; p += 4) {
                float w0 = Ws4[(100 + p) * 400 + j], w1 = Ws4[(101 + p) * 400 + j];
                float w2 = Ws4[(102 + p) * 400 + j], w3 = Ws4[(103 + p) * 400 + j];
#pragma unroll
                for (int n = 0; n < NT; n++) {
                    float4 sv = *(const float4*)&vn[n][p];
                    acc[n] = fmaf(sv.x, w0, fmaf(sv.y, w1, fmaf(sv.z, w2, fmaf(sv.w, w3, acc[n]))));
                }
            }
#pragma unroll
            for (int n = 0; n < NT; n++) s4[n][j] = fmaxf(acc[n], 0.0f);
        }
    }
    __syncthreads();

    for (int idx = tid; idx < NT * 32; idx += 128) {
        int n = idx >> 5, o = idx & 31;
        float a0 = 0.f, a1 = 0.f, a2 = 0.f;
#pragma unroll
        for (int h = 0; h < 32; h++) {
            float w = Wv4s[h * 32 + o];
            a0 = fmaf(vh[n][3 * h], w, a0); a1 = fmaf(vh[n][3 * h + 1], w, a1); a2 = fmaf(vh[n][3 * h + 2], w, a2);
        }
        float nn = sqrtf(fmaf(a0, a0, fmaf(a1, a1, a2 * a2)) + 1e-8f);
        float g = sigmoidf_(nn);
        v4[n][o * 3] = a0 * g; v4[n][o * 3 + 1] = a1 * g; v4[n][o * 3 + 2] = a2 * g;
    }
    __syncthreads();

    for (int idx = tid; idx < NT * 32; idx += 128) {
        int n = idx >> 5, h = idx & 31;
        float a0 = 0.f, a1 = 0.f, a2 = 0.f;
#pragma unroll
        for (int i = 0; i < 32; i++) {
            float w = Wh5s[i * 32 + h];
            a0 = fmaf(v4[n][3 * i], w, a0); a1 = fmaf(v4[n][3 * i + 1], w, a1); a2 = fmaf(v4[n][3 * i + 2], w, a2);
        }
        vh[n][h * 3] = a0; vh[n][h * 3 + 1] = a1; vh[n][h * 3 + 2] = a2;
        vn[n][h] = sqrtf(fmaf(a0, a0, fmaf(a1, a1, a2 * a2)) + 1e-8f);
    }
    __syncthreads();

    if (tid < 100) {
        int j = tid;
        float acc[NT];
        float b = bs5[j];
#pragma unroll
        for (int n = 0; n < NT; n++) acc[n] = b;
#pragma unroll 2
        for (int p = 0; p < 400; p += 4) {
            float w0 = Ws5[(p + 0) * 100 + j], w1 = Ws5[(p + 1) * 100 + j];
            float w2 = Ws5[(p + 2) * 100 + j], w3 = Ws5[(p + 3) * 100 + j];
#pragma unroll
            for (int n = 0; n < NT; n++) {
                float4 sv = *(const float4*)&s4[n][p];
                acc[n] = fmaf(sv.x, w0, fmaf(sv.y, w1, fmaf(sv.z, w2, fmaf(sv.w, w3, acc[n]))));
            }
        }
#pragma unroll 2
        for (int p = 0; p < 32; p += 4) {
            float w0 = Ws5[(400 + p) * 100 + j], w1 = Ws5[(401 + p) * 100 + j];
            float w2 = Ws5[(402 + p) * 100 + j], w3 = Ws5[(403 + p) * 100 + j];
#pragma unroll
            for (int n = 0; n < NT; n++) {
                float4 sv = *(const float4*)&vn[n][p];
                acc[n] = fmaf(sv.x, w0, fmaf(sv.y, w1, fmaf(sv.z, w2, fmaf(sv.w, w3, acc[n]))));
            }
        }
#pragma unroll
        for (int n = 0; n < NT; n++) s5[n][j] = acc[n];
    }
    __syncthreads();

    {
        int n = tid >> 4, o = tid & 15;
        float a0 = 0.f, a1 = 0.f, a2 = 0.f;
#pragma unroll
        for (int h = 0; h < 32; h++) {
            float w = Wv5s[h * 16 + o];
            a0 = fmaf(vh[n][3 * h], w, a0); a1 = fmaf(vh[n][3 * h + 1], w, a1); a2 = fmaf(vh[n][3 * h + 2], w, a2);
        }
        v5[n][o * 3] = a0; v5[n][o * 3 + 1] = a1; v5[n][o * 3 + 2] = a2;
    }
    __syncthreads();

    {
        int n = tid >> 4, l = tid & 15;
        float* xb = hbuf[n];
        float x0 = xb[3 * l] + v5[n][3 * l];
        float x1 = xb[3 * l + 1] + v5[n][3 * l + 1];
        float x2 = xb[3 * l + 2] + v5[n][3 * l + 2];
        float vv = fmaf(x0, x0, fmaf(x1, x1, x2 * x2));
#pragma unroll
        for (int o = 8; o > 0; o >>= 1) vv += __shfl_xor_sync(0xffffffffu, vv, o, 16);
        float rden = rsqrtf(vv * (1.0f / 16.0f) + 1e-8f);
        float sum = 0.f, sum2 = 0.f;
        float svv[7];
        int cnt = 0;
        for (int p = l; p < 100; p += 16) {
            float v = xb[48 + p] + s5[n][p];
            svv[cnt++] = v;
            sum += v; sum2 = fmaf(v, v, sum2);
        }
#pragma unroll
        for (int o = 8; o > 0; o >>= 1) {
            sum  += __shfl_xor_sync(0xffffffffu, sum, o, 16);
            sum2 += __shfl_xor_sync(0xffffffffu, sum2, o, 16);
        }
        float mu = sum * 0.01f;
        float var = sum2 * 0.01f - mu * mu;
        float rstd = rsqrtf(var + 1e-5f);
        float mk = (float)maskV[nb + n];
        float* op = out + (size_t)(nb + n) * CH;
        op[3 * l]     = mk * x0 * rden;
        op[3 * l + 1] = mk * x1 * rden;
        op[3 * l + 2] = mk * x2 * rden;
        cnt = 0;
        for (int p = l; p < 100; p += 16)
            op[48 + p] = mk * fmaf((svv[cnt++] - mu) * rstd, ln1g[p], ln1b[p]);
    }
}

// no-op pads: keep the ncu sample (in-call position 3) on vec_kernel
__global__ void pad_kernel() {}

extern "C" void kernel_launch(void* const* d_in, const int* in_sizes, int n_in,
                              void* d_out, int out_size) {
    const float* hV    = (const float*)d_in[0];
    const float* hM    = (const float*)d_in[1];
    const int*   maskV = (const int*)d_in[2];
    const int*   maskA = (const int*)d_in[3];
    const float* Wh1 = (const float*)d_in[4];
    const float* Wv1 = (const float*)d_in[5];
    const float* Ws1 = (const float*)d_in[6];
    const float* bs1 = (const float*)d_in[7];
    const float* Wh2 = (const float*)d_in[8];
    const float* Wv2 = (const float*)d_in[9];
    const float* Ws2 = (const float*)d_in[10];
    const float* bs2 = (const float*)d_in[11];
    const float* Wh3 = (const float*)d_in[12];
    const float* Wv3 = (const float*)d_in[13];
    const float* Ws3 = (const float*)d_in[14];
    const float* bs3 = (const float*)d_in[15];
    const float* Wh4 = (const float*)d_in[16];
    const float* Wv4 = (const float*)d_in[17];
    const float* Ws4 = (const float*)d_in[18];
    const float* bs4 = (const float*)d_in[19];
    const float* Wh5 = (const float*)d_in[20];
    const float* Wv5 = (const float*)d_in[21];
    const float* Ws5 = (const float*)d_in[22];
    const float* bs5 = (const float*)d_in[23];
    const float* ln0g = (const float*)d_in[24];
    const float* ln0b = (const float*)d_in[25];
    const float* ln1g = (const float*)d_in[26];
    const float* ln1b = (const float*)d_in[27];
    float* out = (float*)d_out;

    float* s1p; cudaGetSymbolAddress((void**)&s1p, g_s1);
    float* s2p; cudaGetSymbolAddress((void**)&s2p, g_s2);
    float* vn1p; cudaGetSymbolAddress((void**)&vn1p, g_vn1);
    float* vn2p; cudaGetSymbolAddress((void**)&vn2p, g_vn2);
    float* vn3p; cudaGetSymbolAddress((void**)&vn3p, g_vn3);
    float* sVsp; cudaGetSymbolAddress((void**)&sVsp, g_sVs);
    float* b1h; cudaGetSymbolAddress((void**)&b1h, g_B1hi);
    float* b1l; cudaGetSymbolAddress((void**)&b1l, g_B1lo);
    float* b2h; cudaGetSymbolAddress((void**)&b2h, g_B2hi);
    float* b2l; cudaGetSymbolAddress((void**)&b2l, g_B2lo);
    float* b3h; cudaGetSymbolAddress((void**)&b3h, g_B3hi);
    float* b3l; cudaGetSymbolAddress((void**)&b3l, g_B3lo);

    const int smemA = VA_TOT * 4;
    const int smemG1 = 2 * 17 * 8 * 104 * 4;
    const int smemG23 = 2 * 15 * 8 * 104 * 4;
    cudaFuncSetAttribute(vec_kernel, cudaFuncAttributeMaxDynamicSharedMemorySize, smemA);
    cudaFuncSetAttribute(gemm_kernel<17, 32, true, true>,
                         cudaFuncAttributeMaxDynamicSharedMemorySize, smemG1);
    cudaFuncSetAttribute(gemm_kernel<15, 16, true, false>,
                         cudaFuncAttributeMaxDynamicSharedMemorySize, smemG23);
    cudaFuncSetAttribute(gemm_kernel<15, 16, false, false>,
                         cudaFuncAttributeMaxDynamicSharedMemorySize, smemG23);

    pad_kernel<<<1, 32>>>();
    pad_kernel<<<1, 32>>>();
    prep_kernel<<<52, 256>>>(Ws1, Ws2, Ws3);
    vec_kernel<<<NNODE, 128, smemA>>>(hV, hM, maskA, Wh1, Wv1, Ws1, bs1,
                                      Wh2, Wv2, Wh3, Wv3);
    gemm_kernel<17, 32, true, true><<<NEDGE / 256, 512, smemG1>>>(
        hM, CH, 48, vn1p, b1h, b1l, sVsp, s1p);
    gemm_kernel<15, 16, true, false><<<NEDGE / 256, 512, smemG23>>>(
        s1p, 100, 0, vn2p, b2h, b2l, bs2, s2p);
    gemm_kernel<15, 16, false, false><<<NEDGE / 256, 512, smemG23>>>(
        s2p, 100, 0, vn3p, b3h, b3l, bs3, s1p);
    reduce_kernel<<<NNODE, 128>>>(maskA, s1p);
    node_kernel<<<NNODE / NT, 128>>>(
        hV, maskV, Wh4, Wv4, Ws4, bs4, Wh5, Wv5, Ws5, bs5,
        ln0g, ln0b, ln1g, ln1b, out);
}

// round 16
// speedup vs baseline: 1.7091x; 1.2140x over previous
#include <cuda_runtime.h>

#define KK 30
#define NNODE 16384
#define NEDGE (NNODE * KK)   // 491520
#define CH 148
#define NT 8

// ---------------- device scratch (no allocation) ----------------
__device__ float g_dh[(size_t)NNODE * CH];
__device__ float g_sVs[(size_t)NNODE * 100];
__device__ float g_vn1[(size_t)NEDGE * 32];
__device__ float g_vn2[(size_t)NEDGE * 16];
__device__ float g_vn3[(size_t)NEDGE * 16];
__device__ float g_s1[(size_t)NEDGE * 100];
__device__ float g_s2[(size_t)NEDGE * 100];
// B planes (bf16x2 hi/lo, row-pair packed): idx = (kstep*8 + prow)*104 + n,
// word = bf16x2( W[16ks+2p][n], W[16ks+2p+1][n] ). KS1=9 (K=144), KS23=8 (K=128).
__device__ unsigned g_B1hi[9 * 8 * 104], g_B1lo[9 * 8 * 104];
__device__ unsigned g_B2hi[8 * 8 * 104], g_B2lo[8 * 8 * 104];
__device__ unsigned g_B3hi[8 * 8 * 104], g_B3lo[8 * 8 * 104];

__device__ __forceinline__ float sigmoidf_(float x) { return 1.0f / (1.0f + expf(-x)); }

// pack two f32 -> bf16x2 (lo -> bits[0:16), hi -> bits[16:32))
__device__ __forceinline__ unsigned bf16x2_pack(float lo, float hi) {
    unsigned u; asm("cvt.rn.bf16x2.f32 %0, %1, %2;" : "=r"(u) : "f"(hi), "f"(lo)); return u;
}
__device__ __forceinline__ float bf16x2_lowf(unsigned u)  { return __uint_as_float(u << 16); }
__device__ __forceinline__ float bf16x2_highf(unsigned u) { return __uint_as_float(u & 0xffff0000u); }

__device__ __forceinline__ void mma_bf16(float& c0, float& c1, float& c2, float& c3,
                                         unsigned a0, unsigned a1, unsigned a2, unsigned a3,
                                         unsigned b0, unsigned b1) {
    asm volatile("mma.sync.aligned.m16n8k16.row.col.f32.bf16.bf16.f32 "
                 "{%0,%1,%2,%3},{%4,%5,%6,%7},{%8,%9},{%0,%1,%2,%3};"
                 : "+f"(c0), "+f"(c1), "+f"(c2), "+f"(c3)
                 : "r"(a0), "r"(a1), "r"(a2), "r"(a3), "r"(b0), "r"(b1));
}

// ---------------- prep: bf16 hi/lo planes, row-pair packed ----------------
__global__ void prep_kernel(const float* __restrict__ Ws1,
                            const float* __restrict__ Ws2,
                            const float* __restrict__ Ws3) {
    int tid = blockIdx.x * blockDim.x + threadIdx.x;
    int stride = gridDim.x * blockDim.x;
    for (int idx = tid; idx < 9 * 8 * 104; idx += stride) {
        int p = idx / 104, n = idx - p * 104;
        int k0 = (p >> 3) * 16 + (p & 7) * 2;
        float v0 = (k0 < 132 && n < 100) ? Ws1[(size_t)(100 + k0) * 100 + n] : 0.f;
        float v1 = (k0 + 1 < 132 && n < 100) ? Ws1[(size_t)(101 + k0) * 100 + n] : 0.f;
        unsigned hi = bf16x2_pack(v0, v1);
        g_B1hi[idx] = hi;
        g_B1lo[idx] = bf16x2_pack(v0 - bf16x2_lowf(hi), v1 - bf16x2_highf(hi));
    }
    for (int idx = tid; idx < 8 * 8 * 104; idx += stride) {
        int p = idx / 104, n = idx - p * 104;
        int k0 = (p >> 3) * 16 + (p & 7) * 2;
        float v0 = (k0 < 116 && n < 100) ? Ws2[(size_t)k0 * 100 + n] : 0.f;
        float v1 = (k0 + 1 < 116 && n < 100) ? Ws2[(size_t)(k0 + 1) * 100 + n] : 0.f;
        unsigned hi = bf16x2_pack(v0, v1);
        g_B2hi[idx] = hi;
        g_B2lo[idx] = bf16x2_pack(v0 - bf16x2_lowf(hi), v1 - bf16x2_highf(hi));
        float u0 = (k0 < 116 && n < 100) ? Ws3[(size_t)k0 * 100 + n] : 0.f;
        float u1 = (k0 + 1 < 116 && n < 100) ? Ws3[(size_t)(k0 + 1) * 100 + n] : 0.f;
        unsigned hi3 = bf16x2_pack(u0, u1);
        g_B3hi[idx] = hi3;
        g_B3lo[idx] = bf16x2_pack(u0 - bf16x2_lowf(hi3), u1 - bf16x2_highf(hi3));
    }
}

// ---------------- vector-track kernel (per node, unchanged) ----------------
template <int NI, int NH>
__device__ __forceinline__ void vh_stage(
    const float* __restrict__ vin, int vinstride,
    const float* __restrict__ Wh, const float* __restrict__ init,
    float* __restrict__ vh, int vhstride,
    float* __restrict__ vn_g, int tid)
{
    for (int idx = tid; idx < KK * NH; idx += 128) {
        int e = idx / NH;
        int h = idx - e * NH;
        float a0 = 0.f, a1 = 0.f, a2 = 0.f;
        if (init) { a0 = init[h * 3 + 0]; a1 = init[h * 3 + 1]; a2 = init[h * 3 + 2]; }
        const float4* vp4 = (const float4*)(vin + e * vinstride);
#pragma unroll
        for (int q = 0; q < NI / 4; q++) {
            float4 A = vp4[3 * q + 0];
            float4 B = vp4[3 * q + 1];
            float4 C = vp4[3 * q + 2];
            float w0 = Wh[(4 * q + 0) * NH + h];
            float w1 = Wh[(4 * q + 1) * NH + h];
            float w2 = Wh[(4 * q + 2) * NH + h];
            float w3 = Wh[(4 * q + 3) * NH + h];
            a0 = fmaf(A.x, w0, a0); a1 = fmaf(A.y, w0, a1); a2 = fmaf(A.z, w0, a2);
            a0 = fmaf(A.w, w1, a0); a1 = fmaf(B.x, w1, a1); a2 = fmaf(B.y, w1, a2);
            a0 = fmaf(B.z, w2, a0); a1 = fmaf(B.w, w2, a1); a2 = fmaf(C.x, w2, a2);
            a0 = fmaf(C.y, w3, a0); a1 = fmaf(C.z, w3, a1); a2 = fmaf(C.w, w3, a2);
        }
        float* vo = vh + e * vhstride + h * 3;
        vo[0] = a0; vo[1] = a1; vo[2] = a2;
        vn_g[(size_t)e * NH + h] = sqrtf(fmaf(a0, a0, fmaf(a1, a1, a2 * a2)) + 1e-8f);
    }
}

template <int NH, bool GATE>
__device__ __forceinline__ void vout_stage(
    const float* __restrict__ vh, int vhstride,
    const float* __restrict__ Wv, float* __restrict__ vout, int tid)
{
    for (int idx = tid; idx < KK * 16; idx += 128) {
        int e = idx >> 4;
        int o = idx & 15;
        float a0 = 0.f, a1 = 0.f, a2 = 0.f;
        const float4* vp4 = (const float4*)(vh + e * vhstride);
#pragma unroll
        for (int q = 0; q < NH / 4; q++) {
            float4 A = vp4[3 * q + 0];
            float4 B = vp4[3 * q + 1];
            float4 C = vp4[3 * q + 2];
            float w0 = Wv[(4 * q + 0) * 16 + o];
            float w1 = Wv[(4 * q + 1) * 16 + o];
            float w2 = Wv[(4 * q + 2) * 16 + o];
            float w3 = Wv[(4 * q + 3) * 16 + o];
            a0 = fmaf(A.x, w0, a0); a1 = fmaf(A.y, w0, a1); a2 = fmaf(A.z, w0, a2);
            a0 = fmaf(A.w, w1, a0); a1 = fmaf(B.x, w1, a1); a2 = fmaf(B.y, w1, a2);
            a0 = fmaf(B.z, w2, a0); a1 = fmaf(B.w, w2, a1); a2 = fmaf(C.x, w2, a2);
            a0 = fmaf(C.y, w3, a0); a1 = fmaf(C.z, w3, a1); a2 = fmaf(C.w, w3, a2);
        }
        if (GATE) {
            float n = sqrtf(fmaf(a0, a0, fmaf(a1, a1, a2 * a2)) + 1e-8f);
            float g = sigmoidf_(n);
            a0 *= g; a1 *= g; a2 *= g;
        }
        float* vo = vout + e * 48 + o * 3;
        vo[0] = a0; vo[1] = a1; vo[2] = a2;
    }
}

// smem offsets (floats) -- all float4-aligned
#define VA_VM   0
#define VA_VH   1440
#define VA_V    4320
#define VA_HV   5760
#define VA_VVH  5912
#define VA_MASK 6008
#define VA_WH1  6040
#define VA_WV1  7064
#define VA_WH2  7576
#define VA_WV2  7832
#define VA_WH3  8088
#define VA_WV3  8344
#define VA_TOT  8600

__global__ void __launch_bounds__(128, 5) vec_kernel(
    const float* __restrict__ hV, const float* __restrict__ hM,
    const int* __restrict__ maskA,
    const float* __restrict__ Wh1, const float* __restrict__ Wv1,
    const float* __restrict__ Ws1, const float* __restrict__ bs1,
    const float* __restrict__ Wh2, const float* __restrict__ Wv2,
    const float* __restrict__ Wh3, const float* __restrict__ Wv3)
{
    extern __shared__ float sm[];
    float* vM_s  = sm + VA_VM;
    float* vh_s  = sm + VA_VH;
    float* v_s   = sm + VA_V;
    float* hV_s  = sm + VA_HV;
    float* vVh_s = sm + VA_VVH;
    float* mask_s= sm + VA_MASK;
    float* Wh1_s = sm + VA_WH1;
    float* Wv1_s = sm + VA_WV1;
    float* Wh2_s = sm + VA_WH2;
    float* Wv2_s = sm + VA_WV2;
    float* Wh3_s = sm + VA_WH3;
    float* Wv3_s = sm + VA_WV3;

    const int tid = threadIdx.x;
    const int node = blockIdx.x;
    const float* hMb = hM + (size_t)node * KK * CH;

    for (int idx = tid; idx < KK * 12; idx += 128) {
        int e = idx / 12, q = idx - e * 12;
        *(float4*)&vM_s[e * 48 + q * 4] = *(const float4*)(hMb + (size_t)e * CH + q * 4);
    }
    for (int i = tid; i < CH; i += 128) hV_s[i] = hV[(size_t)node * CH + i];
    if (tid < KK) mask_s[tid] = (float)maskA[(size_t)node * KK + tid];
    for (int i = tid; i < 1024; i += 128) Wh1_s[i] = Wh1[i];
    for (int i = tid; i < 512; i += 128) Wv1_s[i] = Wv1[i];
    for (int i = tid; i < 256; i += 128) {
        Wh2_s[i] = Wh2[i]; Wv2_s[i] = Wv2[i];
        Wh3_s[i] = Wh3[i]; Wv3_s[i] = Wv3[i];
    }
    __syncthreads();

    if (tid < 96) {
        int h = tid / 3, c = tid - h * 3;
        float a = 0.f;
#pragma unroll
        for (int i = 0; i < 16; i++) a = fmaf(hV_s[3 * i + c], Wh1_s[i * 32 + h], a);
        vVh_s[h * 3 + c] = a;
    }
    if (tid < 100) {
        float a = bs1[tid];
#pragma unroll 4
        for (int p = 0; p < 100; p++) a = fmaf(hV_s[48 + p], Ws1[(size_t)p * 100 + tid], a);
        g_sVs[(size_t)node * 100 + tid] = a;
    }
    __syncthreads();

    vh_stage<16, 32>(vM_s, 48, Wh1_s + 16 * 32, vVh_s, vh_s, 96,
                     g_vn1 + (size_t)node * KK * 32, tid);
    __syncthreads();
    vout_stage<32, true>(vh_s, 96, Wv1_s, v_s, tid);
    __syncthreads();
    vh_stage<16, 16>(v_s, 48, Wh2_s, nullptr, vh_s, 48,
                     g_vn2 + (size_t)node * KK * 16, tid);
    __syncthreads();
    vout_stage<16, true>(vh_s, 48, Wv2_s, v_s, tid);
    __syncthreads();
    vh_stage<16, 16>(v_s, 48, Wh3_s, nullptr, vh_s, 48,
                     g_vn3 + (size_t)node * KK * 16, tid);
    __syncthreads();
    vout_stage<16, false>(vh_s, 48, Wv3_s, v_s, tid);
    __syncthreads();

    if (tid < 48) {
        float a = 0.f;
#pragma unroll
        for (int e = 0; e < KK; e++) a = fmaf(mask_s[e], v_s[e * 48 + tid], a);
        g_dh[(size_t)node * CH + tid] = a * (1.0f / 30.0f);
    }
}

// ---------------- bf16-split 3x GEMM over all edges (m16n8k16) ----------------
template <int W2>
__device__ __forceinline__ float2 loadA2(const float* __restrict__ srcS, int strideS, int offS,
                                         const float* __restrict__ srcV, int r, int c)
{
    if (c < 100) return *(const float2*)(srcS + (size_t)r * strideS + offS + c);
    if (c < 100 + W2) return *(const float2*)(srcV + (size_t)r * W2 + (c - 100));
    return make_float2(0.f, 0.f);
}

template <int KSTEPS, int W2, bool RELU, bool INIT_SVS, int NJ>
__device__ __forceinline__ void gemm_core(
    const float* __restrict__ srcS, int strideS, int offS,
    const float* __restrict__ srcV,
    const unsigned* Bhi, const unsigned* Blo,
    const float* __restrict__ initv,
    float* __restrict__ outp,
    int m0, int j0, int gid, int tig)
{
    float acc[2][NJ][4] = {};
    float2 fcur[2][4];
#pragma unroll
    for (int t = 0; t < 2; t++) {
        int r0 = m0 + t * 16 + gid, r1 = r0 + 8;
        int c0 = 2 * tig;
        fcur[t][0] = loadA2<W2>(srcS, strideS, offS, srcV, r0, c0);
        fcur[t][1] = loadA2<W2>(srcS, strideS, offS, srcV, r1, c0);
        fcur[t][2] = loadA2<W2>(srcS, strideS, offS, srcV, r0, c0 + 8);
        fcur[t][3] = loadA2<W2>(srcS, strideS, offS, srcV, r1, c0 + 8);
    }
#pragma unroll 1
    for (int k = 0; k < KSTEPS; k++) {
        unsigned ahi[2][4], alo[2][4];
#pragma unroll
        for (int t = 0; t < 2; t++)
#pragma unroll
            for (int q = 0; q < 4; q++) {
                float2 f = fcur[t][q];
                unsigned h = bf16x2_pack(f.x, f.y);
                ahi[t][q] = h;
                alo[t][q] = bf16x2_pack(f.x - bf16x2_lowf(h), f.y - bf16x2_highf(h));
            }
        if (k + 1 < KSTEPS) {
#pragma unroll
            for (int t = 0; t < 2; t++) {
                int r0 = m0 + t * 16 + gid, r1 = r0 + 8;
                int c0 = (k + 1) * 16 + 2 * tig;
                fcur[t][0] = loadA2<W2>(srcS, strideS, offS, srcV, r0, c0);
                fcur[t][1] = loadA2<W2>(srcS, strideS, offS, srcV, r1, c0);
                fcur[t][2] = loadA2<W2>(srcS, strideS, offS, srcV, r0, c0 + 8);
                fcur[t][3] = loadA2<W2>(srcS, strideS, offS, srcV, r1, c0 + 8);
            }
        }
#pragma unroll
        for (int jj = 0; jj < NJ; jj++) {
            int n0 = (j0 + jj) * 8 + gid;
            unsigned bh0 = Bhi[(k * 8 + tig) * 104 + n0];
            unsigned bh1 = Bhi[(k * 8 + tig + 4) * 104 + n0];
            unsigned bl0 = Blo[(k * 8 + tig) * 104 + n0];
            unsigned bl1 = Blo[(k * 8 + tig + 4) * 104 + n0];
#pragma unroll
            for (int t = 0; t < 2; t++) {
                mma_bf16(acc[t][jj][0], acc[t][jj][1], acc[t][jj][2], acc[t][jj][3],
                         ahi[t][0], ahi[t][1], ahi[t][2], ahi[t][3], bh0, bh1);
                mma_bf16(acc[t][jj][0], acc[t][jj][1], acc[t][jj][2], acc[t][jj][3],
                         ahi[t][0], ahi[t][1], ahi[t][2], ahi[t][3], bl0, bl1);
                mma_bf16(acc[t][jj][0], acc[t][jj][1], acc[t][jj][2], acc[t][jj][3],
                         alo[t][0], alo[t][1], alo[t][2], alo[t][3], bh0, bh1);
            }
        }
    }
#pragma unroll
    for (int t = 0; t < 2; t++) {
        int r0 = m0 + t * 16 + gid, r1 = r0 + 8;
#pragma unroll
        for (int jj = 0; jj < NJ; jj++) {
            int c0 = (j0 + jj) * 8 + tig * 2;
            if (c0 < 100) {
                float i00, i01, i10, i11;
                if (INIT_SVS) {
                    const float* p0 = initv + (size_t)(r0 / 30) * 100;
                    const float* p1 = initv + (size_t)(r1 / 30) * 100;
                    i00 = p0[c0]; i01 = p0[c0 + 1];
                    i10 = p1[c0]; i11 = p1[c0 + 1];
                } else {
                    i00 = initv[c0]; i01 = initv[c0 + 1];
                    i10 = i00; i11 = i01;
                }
                float v00 = acc[t][jj][0] + i00;
                float v01 = acc[t][jj][1] + i01;
                float v10 = acc[t][jj][2] + i10;
                float v11 = acc[t][jj][3] + i11;
                if (RELU) {
                    v00 = fmaxf(v00, 0.f); v01 = fmaxf(v01, 0.f);
                    v10 = fmaxf(v10, 0.f); v11 = fmaxf(v11, 0.f);
                }
                *(float2*)&outp[(size_t)r0 * 100 + c0] = make_float2(v00, v01);
                *(float2*)&outp[(size_t)r1 * 100 + c0] = make_float2(v10, v11);
            }
        }
    }
}

template <int KSTEPS, int W2, bool RELU, bool INIT_SVS>
__global__ void __launch_bounds__(512, 1) gemm_kernel(
    const float* __restrict__ srcS, int strideS, int offS,
    const float* __restrict__ srcV,
    const unsigned* __restrict__ Bhi_g, const unsigned* __restrict__ Blo_g,
    const float* __restrict__ initv,
    float* __restrict__ outp)
{
    extern __shared__ unsigned smemB[];
    unsigned* Bhi = smemB;
    unsigned* Blo = smemB + KSTEPS * 8 * 104;
    const int tid = threadIdx.x;
    const int nB = KSTEPS * 8 * 104;
    for (int i = tid * 4; i < nB; i += 512 * 4) {
        *(uint4*)&Bhi[i] = *(const uint4*)&Bhi_g[i];
        *(uint4*)&Blo[i] = *(const uint4*)&Blo_g[i];
    }
    __syncthreads();

    const int warp = tid >> 5, lane = tid & 31;
    const int gid = lane >> 2, tig = lane & 3;
    const int mw = warp & 7, ng = warp >> 3;
    const int m0 = blockIdx.x * 256 + mw * 32;

    if (ng == 0)
        gemm_core<KSTEPS, W2, RELU, INIT_SVS, 7>(srcS, strideS, offS, srcV,
                                                 Bhi, Blo, initv, outp, m0, 0, gid, tig);
    else
        gemm_core<KSTEPS, W2, RELU, INIT_SVS, 6>(srcS, strideS, offS, srcV,
                                                 Bhi, Blo, initv, outp, m0, 7, gid, tig);
}

// ---------------- masked mean of s3 -> g_dh scalar part ----------------
__global__ void __launch_bounds__(128) reduce_kernel(const int* __restrict__ maskA,
                                                     const float* __restrict__ s3)
{
    int node = blockIdx.x;
    int j = threadIdx.x;
    if (j < 100) {
        const float* base = s3 + (size_t)node * KK * 100 + j;
        const int* mb = maskA + (size_t)node * KK;
        float a = 0.f;
#pragma unroll
        for (int e = 0; e < KK; e++) a = fmaf((float)mb[e], base[(size_t)e * 100], a);
        g_dh[(size_t)node * CH + 48 + j] = a * (1.0f / 30.0f);
    }
}

// ---------------- node kernel (unchanged) ----------------
__global__ void __launch_bounds__(128, 4) node_kernel(
    const float* __restrict__ hV, const int* __restrict__ maskV,
    const float* __restrict__ Wh4, const float* __restrict__ Wv4,
    const float* __restrict__ Ws4, const float* __restrict__ bs4,
    const float* __restrict__ Wh5, const float* __restrict__ Wv5,
    const float* __restrict__ Ws5, const float* __restrict__ bs5,
    const float* __restrict__ ln0g, const float* __restrict__ ln0b,
    const float* __restrict__ ln1g, const float* __restrict__ ln1b,
    float* __restrict__ out)
{
    __shared__ __align__(16) float hbuf[NT][CH];
    __shared__ __align__(16) float vh[NT][96];
    __shared__ __align__(16) float vn[NT][32];
    __shared__ __align__(16) float s4[NT][400];
    __shared__ __align__(16) float v4[NT][96];
    __shared__ __align__(16) float s5[NT][100];
    __shared__ __align__(16) float v5[NT][48];
    __shared__ float Wh4s[512], Wv4s[1024], Wh5s[1024], Wv5s[512];

    const int tid = threadIdx.x;
    const int nb = blockIdx.x * NT;

    for (int i = tid; i < 512; i += 128) { Wh4s[i] = Wh4[i]; Wv5s[i] = Wv5[i]; }
    for (int i = tid; i < 1024; i += 128) { Wv4s[i] = Wv4[i]; Wh5s[i] = Wh5[i]; }
    for (int idx = tid; idx < NT * CH; idx += 128) {
        int n = idx / CH, c = idx - n * CH;
        hbuf[n][c] = hV[(size_t)(nb + n) * CH + c] + g_dh[(size_t)(nb + n) * CH + c];
    }
    __syncthreads();

    {
        int n = tid >> 4, l = tid & 15;
        float* xb = hbuf[n];
        float x0 = xb[3 * l], x1 = xb[3 * l + 1], x2 = xb[3 * l + 2];
        float vv = fmaf(x0, x0, fmaf(x1, x1, x2 * x2));
#pragma unroll
        for (int o = 8; o > 0; o >>= 1) vv += __shfl_xor_sync(0xffffffffu, vv, o, 16);
        float rden = rsqrtf(vv * (1.0f / 16.0f) + 1e-8f);
        float sum = 0.f, sum2 = 0.f;
        for (int p = l; p < 100; p += 16) { float v = xb[48 + p]; sum += v; sum2 = fmaf(v, v, sum2); }
#pragma unroll
        for (int o = 8; o > 0; o >>= 1) {
            sum  += __shfl_xor_sync(0xffffffffu, sum, o, 16);
            sum2 += __shfl_xor_sync(0xffffffffu, sum2, o, 16);
        }
        float mu = sum * 0.01f;
        float var = sum2 * 0.01f - mu * mu;
        float rstd = rsqrtf(var + 1e-5f);
        xb[3 * l] = x0 * rden; xb[3 * l + 1] = x1 * rden; xb[3 * l + 2] = x2 * rden;
        for (int p = l; p < 100; p += 16)
            xb[48 + p] = fmaf((xb[48 + p] - mu) * rstd, ln0g[p], ln0b[p]);
    }
    __syncthreads();

    for (int idx = tid; idx < NT * 32; idx += 128) {
        int n = idx >> 5, h = idx & 31;
        float a0 = 0.f, a1 = 0.f, a2 = 0.f;
        const float* vp = hbuf[n];
#pragma unroll
        for (int i = 0; i < 16; i++) {
            float w = Wh4s[i * 32 + h];
            a0 = fmaf(vp[3 * i], w, a0); a1 = fmaf(vp[3 * i + 1], w, a1); a2 = fmaf(vp[3 * i + 2], w, a2);
        }
        vh[n][h * 3] = a0; vh[n][h * 3 + 1] = a1; vh[n][h * 3 + 2] = a2;
        vn[n][h] = sqrtf(fmaf(a0, a0, fmaf(a1, a1, a2 * a2)) + 1e-8f);
    }
    __syncthreads();

    for (int r = 0; r < 4; r++) {
        int j = r * 128 + tid;
        if (j < 400) {
            float acc[NT];
            float b = bs4[j];
#pragma unroll
            for (int n = 0; n < NT; n++) acc[n] = b;
#pragma unroll 2
            for (int p = 0; p < 100; p += 4) {
                float w0 = Ws4[(p + 0) * 400 + j], w1 = Ws4[(p + 1) * 400 + j];
                float w2 = Ws4[(p + 2) * 400 + j], w3 = Ws4[(p + 3) * 400 + j];
#pragma unroll
                for (int n = 0; n < NT; n++) {
                    float4 sv = *(const float4*)&hbuf[n][48 + p];
                    acc[n] = fmaf(sv.x, w0, fmaf(sv.y, w1, fmaf(sv.z, w2, fmaf(sv.w, w3, acc[n]))));
                }
            }
#pragma unroll 2
            for (int p = 0; p < 32; p += 4) {
                float w0 = Ws4[(100 + p) * 400 + j], w1 = Ws4[(101 + p) * 400 + j];
                float w2 = Ws4[(102 + p) * 400 + j], w3 = Ws4[(103 + p) * 400 + j];
#pragma unroll
                for (int n = 0; n < NT; n++) {
                    float4 sv = *(const float4*)&vn[n][p];
                    acc[n] = fmaf(sv.x, w0, fmaf(sv.y, w1, fmaf(sv.z, w2, fmaf(sv.w, w3, acc[n]))));
                }
            }
#pragma unroll
            for (int n = 0; n < NT; n++) s4[n][j] = fmaxf(acc[n], 0.0f);
        }
    }
    __syncthreads();

    for (int idx = tid; idx < NT * 32; idx += 128) {
        int n = idx >> 5, o = idx & 31;
        float a0 = 0.f, a1 = 0.f, a2 = 0.f;
#pragma unroll
        for (int h = 0; h < 32; h++) {
            float w = Wv4s[h * 32 + o];
            a0 = fmaf(vh[n][3 * h], w, a0); a1 = fmaf(vh[n][3 * h + 1], w, a1); a2 = fmaf(vh[n][3 * h + 2], w, a2);
        }
        float nn = sqrtf(fmaf(a0, a0, fmaf(a1, a1, a2 * a2)) + 1e-8f);
        float g = sigmoidf_(nn);
        v4[n][o * 3] = a0 * g; v4[n][o * 3 + 1] = a1 * g; v4[n][o * 3 + 2] = a2 * g;
    }
    __syncthreads();

    for (int idx = tid; idx < NT * 32; idx += 128) {
        int n = idx >> 5, h = idx & 31;
        float a0 = 0.f, a1 = 0.f, a2 = 0.f;
#pragma unroll
        for (int i = 0; i < 32; i++) {
            float w = Wh5s[i * 32 + h];
            a0 = fmaf(v4[n][3 * i], w, a0); a1 = fmaf(v4[n][3 * i + 1], w, a1); a2 = fmaf(v4[n][3 * i + 2], w, a2);
        }
        vh[n][h * 3] = a0; vh[n][h * 3 + 1] = a1; vh[n][h * 3 + 2] = a2;
        vn[n][h] = sqrtf(fmaf(a0, a0, fmaf(a1, a1, a2 * a2)) + 1e-8f);
    }
    __syncthreads();

    if (tid < 100) {
        int j = tid;
        float acc[NT];
        float b = bs5[j];
#pragma unroll
        for (int n = 0; n < NT; n++) acc[n] = b;
#pragma unroll 2
        for (int p = 0; p < 400; p += 4) {
            float w0 = Ws5[(p + 0) * 100 + j], w1 = Ws5[(p + 1) * 100 + j];
            float w2 = Ws5[(p + 2) * 100 + j], w3 = Ws5[(p + 3) * 100 + j];
#pragma unroll
            for (int n = 0; n < NT; n++) {
                float4 sv = *(const float4*)&s4[n][p];
                acc[n] = fmaf(sv.x, w0, fmaf(sv.y, w1, fmaf(sv.z, w2, fmaf(sv.w, w3, acc[n]))));
            }
        }
#pragma unroll 2
        for (int p = 0; p < 32; p += 4) {
            float w0 = Ws5[(400 + p) * 100 + j], w1 = Ws5[(401 + p) * 100 + j];
            float w2 = Ws5[(402 + p) * 100 + j], w3 = Ws5[(403 + p) * 100 + j];
#pragma unroll
            for (int n = 0; n < NT; n++) {
                float4 sv = *(const float4*)&vn[n][p];
                acc[n] = fmaf(sv.x, w0, fmaf(sv.y, w1, fmaf(sv.z, w2, fmaf(sv.w, w3, acc[n]))));
            }
        }
#pragma unroll
        for (int n = 0; n < NT; n++) s5[n][j] = acc[n];
    }
    __syncthreads();

    {
        int n = tid >> 4, o = tid & 15;
        float a0 = 0.f, a1 = 0.f, a2 = 0.f;
#pragma unroll
        for (int h = 0; h < 32; h++) {
            float w = Wv5s[h * 16 + o];
            a0 = fmaf(vh[n][3 * h], w, a0); a1 = fmaf(vh[n][3 * h + 1], w, a1); a2 = fmaf(vh[n][3 * h + 2], w, a2);
        }
        v5[n][o * 3] = a0; v5[n][o * 3 + 1] = a1; v5[n][o * 3 + 2] = a2;
    }
    __syncthreads();

    {
        int n = tid >> 4, l = tid & 15;
        float* xb = hbuf[n];
        float x0 = xb[3 * l] + v5[n][3 * l];
        float x1 = xb[3 * l + 1] + v5[n][3 * l + 1];
        float x2 = xb[3 * l + 2] + v5[n][3 * l + 2];
        float vv = fmaf(x0, x0, fmaf(x1, x1, x2 * x2));
#pragma unroll
        for (int o = 8; o > 0; o >>= 1) vv += __shfl_xor_sync(0xffffffffu, vv, o, 16);
        float rden = rsqrtf(vv * (1.0f / 16.0f) + 1e-8f);
        float sum = 0.f, sum2 = 0.f;
        float svv[7];
        int cnt = 0;
        for (int p = l; p < 100; p += 16) {
            float v = xb[48 + p] + s5[n][p];
            svv[cnt++] = v;
            sum += v; sum2 = fmaf(v, v, sum2);
        }
#pragma unroll
        for (int o = 8; o > 0; o >>= 1) {
            sum  += __shfl_xor_sync(0xffffffffu, sum, o, 16);
            sum2 += __shfl_xor_sync(0xffffffffu, sum2, o, 16);
        }
        float mu = sum * 0.01f;
        float var = sum2 * 0.01f - mu * mu;
        float rstd = rsqrtf(var + 1e-5f);
        float mk = (float)maskV[nb + n];
        float* op = out + (size_t)(nb + n) * CH;
        op[3 * l]     = mk * x0 * rden;
        op[3 * l + 1] = mk * x1 * rden;
        op[3 * l + 2] = mk * x2 * rden;
        cnt = 0;
        for (int p = l; p < 100; p += 16)
            op[48 + p] = mk * fmaf((svv[cnt++] - mu) * rstd, ln1g[p], ln1b[p]);
    }
}

extern "C" void kernel_launch(void* const* d_in, const int* in_sizes, int n_in,
                              void* d_out, int out_size) {
    const float* hV    = (const float*)d_in[0];
    const float* hM    = (const float*)d_in[1];
    const int*   maskV = (const int*)d_in[2];
    const int*   maskA = (const int*)d_in[3];
    const float* Wh1 = (const float*)d_in[4];
    const float* Wv1 = (const float*)d_in[5];
    const float* Ws1 = (const float*)d_in[6];
    const float* bs1 = (const float*)d_in[7];
    const float* Wh2 = (const float*)d_in[8];
    const float* Wv2 = (const float*)d_in[9];
    const float* Ws2 = (const float*)d_in[10];
    const float* bs2 = (const float*)d_in[11];
    const float* Wh3 = (const float*)d_in[12];
    const float* Wv3 = (const float*)d_in[13];
    const float* Ws3 = (const float*)d_in[14];
    const float* bs3 = (const float*)d_in[15];
    const float* Wh4 = (const float*)d_in[16];
    const float* Wv4 = (const float*)d_in[17];
    const float* Ws4 = (const float*)d_in[18];
    const float* bs4 = (const float*)d_in[19];
    const float* Wh5 = (const float*)d_in[20];
    const float* Wv5 = (const float*)d_in[21];
    const float* Ws5 = (const float*)d_in[22];
    const float* bs5 = (const float*)d_in[23];
    const float* ln0g = (const float*)d_in[24];
    const float* ln0b = (const float*)d_in[25];
    const float* ln1g = (const float*)d_in[26];
    const float* ln1b = (const float*)d_in[27];
    float* out = (float*)d_out;

    float* s1p; cudaGetSymbolAddress((void**)&s1p, g_s1);
    float* s2p; cudaGetSymbolAddress((void**)&s2p, g_s2);
    float* vn1p; cudaGetSymbolAddress((void**)&vn1p, g_vn1);
    float* vn2p; cudaGetSymbolAddress((void**)&vn2p, g_vn2);
    float* vn3p; cudaGetSymbolAddress((void**)&vn3p, g_vn3);
    float* sVsp; cudaGetSymbolAddress((void**)&sVsp, g_sVs);
    unsigned* b1h; cudaGetSymbolAddress((void**)&b1h, g_B1hi);
    unsigned* b1l; cudaGetSymbolAddress((void**)&b1l, g_B1lo);
    unsigned* b2h; cudaGetSymbolAddress((void**)&b2h, g_B2hi);
    unsigned* b2l; cudaGetSymbolAddress((void**)&b2l, g_B2lo);
    unsigned* b3h; cudaGetSymbolAddress((void**)&b3h, g_B3hi);
    unsigned* b3l; cudaGetSymbolAddress((void**)&b3l, g_B3lo);

    const int smemA = VA_TOT * 4;
    const int smemG1 = 2 * 9 * 8 * 104 * 4;   // 59,904 B
    const int smemG23 = 2 * 8 * 8 * 104 * 4;  // 53,248 B
    cudaFuncSetAttribute(vec_kernel, cudaFuncAttributeMaxDynamicSharedMemorySize, smemA);
    cudaFuncSetAttribute(gemm_kernel<9, 32, true, true>,
                         cudaFuncAttributeMaxDynamicSharedMemorySize, smemG1);
    cudaFuncSetAttribute(gemm_kernel<8, 16, true, false>,
                         cudaFuncAttributeMaxDynamicSharedMemorySize, smemG23);
    cudaFuncSetAttribute(gemm_kernel<8, 16, false, false>,
                         cudaFuncAttributeMaxDynamicSharedMemorySize, smemG23);

    prep_kernel<<<52, 256>>>(Ws1, Ws2, Ws3);
    vec_kernel<<<NNODE, 128, smemA>>>(hV, hM, maskA, Wh1, Wv1, Ws1, bs1,
                                      Wh2, Wv2, Wh3, Wv3);
    gemm_kernel<9, 32, true, true><<<NEDGE / 256, 512, smemG1>>>(
        hM, CH, 48, vn1p, b1h, b1l, sVsp, s1p);
    gemm_kernel<8, 16, true, false><<<NEDGE / 256, 512, smemG23>>>(
        s1p, 100, 0, vn2p, b2h, b2l, bs2, s2p);
    gemm_kernel<8, 16, false, false><<<NEDGE / 256, 512, smemG23>>>(
        s2p, 100, 0, vn3p, b3h, b3l, bs3, s1p);
    reduce_kernel<<<NNODE, 128>>>(maskA, s1p);
    node_kernel<<<NNODE / NT, 128>>>(
        hV, maskV, Wh4, Wv4, Ws4, bs4, Wh5, Wv5, Ws5, bs5,
        ln0g, ln0b, ln1g, ln1b, out);
}